// round 9
// baseline (speedup 1.0000x reference)
#include <cuda_runtime.h>
#include <cuda_bf16.h>
#include <cuda_fp16.h>
#include <math.h>
#include <stdint.h>

#define NN 100000
#define EE 1000000
#define INF 128
#define HH 64
#define BN_EPS 1e-5f

typedef unsigned long long ull;

// ---------------- scratch (device globals, no runtime alloc) ----------------
// Invariant: g_indeg is all-zero at every kernel_launch entry (zero-initialized at
// module load; degscan re-zeros it after use on every execution).
__device__ int   g_indeg[NN];
__device__ int   g_off[NN + 1];
__device__ int   g_rank[EE];
__device__ int   g_csr[EE];
__device__ float g_dinv[NN];
__device__ int   g_bsum[128];
__device__ int   g_boff[128];
__device__ int   g_ticket;
__device__ int   g_flag;
__device__ float g_sum[2][HH];
__device__ float g_sq[2][HH];

__device__ __half2 g_h[(size_t)NN * 32];   // GEMM output (fp16 pairs), pre-scaled by dinv[row]
__device__ float   g_agg[(size_t)NN * HH]; // aggregation output (pre-BN, fp32)

// ---------------- graph build ----------------

// histogram + per-edge rank; also resets per-call scalars/stats (indeg is pre-zeroed)
__global__ void hist_kernel(const int* __restrict__ dst) {
    int e = blockIdx.x * blockDim.x + threadIdx.x;
    if (e < EE) g_rank[e] = atomicAdd(&g_indeg[dst[e]], 1);
    if (e == 0) { g_ticket = 0; g_flag = 0; }
    if (e < 2 * HH) {
        ((float*)g_sum)[e] = 0.f;
        ((float*)g_sq)[e]  = 0.f;
    }
}

// fused: per-block inclusive scan + cross-block scan (last-block election) + finalize
// + self-clean (re-zero indeg). 98 blocks, all resident -> flag spin is safe.
__global__ void degscan_kernel(int nb) {
    __shared__ int sh[1024];
    __shared__ int amLast;
    int t = threadIdx.x;
    int b = blockIdx.x;
    int idx = b * 1024 + t;
    int v = (idx < NN) ? g_indeg[idx] : 0;
    sh[t] = v;
    __syncthreads();
    for (int o = 1; o < 1024; o <<= 1) {
        int a = (t >= o) ? sh[t - o] : 0;
        __syncthreads();
        sh[t] += a;
        __syncthreads();
    }
    int incl = sh[t];
    if (t == 1023) {
        g_bsum[b] = incl;
        __threadfence();
        amLast = (atomicAdd(&g_ticket, 1) == gridDim.x - 1);
    }
    __syncthreads();
    if (amLast) {
        int bv = (t < nb) ? g_bsum[t] : 0;
        sh[t] = (t < 128) ? bv : 0;
        __syncthreads();
        for (int o = 1; o < 128; o <<= 1) {
            int a = (t >= o && t < 128) ? sh[t - o] : 0;
            __syncthreads();
            if (t < 128) sh[t] += a;
            __syncthreads();
        }
        if (t < nb) g_boff[t] = sh[t] - bv;
        if (t == nb - 1) g_off[NN] = sh[t];
        __threadfence();
        if (t == 0) atomicExch(&g_flag, 1);
    }
    if (t == 0) {
        while (atomicAdd(&g_flag, 0) == 0) {}
    }
    __syncthreads();
    if (idx < NN) {
        int off = g_boff[b] + incl - v;
        g_off[idx] = off;
        g_dinv[idx] = rsqrtf((float)(v + 1));   // deg = indeg + self-loop
        g_indeg[idx] = 0;                        // self-clean for next call
    }
}

// ---------------- HMMA GEMM (mma.sync m16n8k16, fp16 in / fp32 accum) ----------------
// h[row] = fp16( dinv[row] * (bn_relu?(A[row]) @ W) ).  Block tile M=128 x N=64.
// DO_BN: scale/shift computed in-block from g_sum[0]/g_sq[0] + gamma/beta.
// DO_FILL: after the tile, this block fills its grid-stride chunk of the CSR
// (independent work overlapped with other blocks' MMA).

__device__ __forceinline__ uint32_t smem_u32(const void* p) {
    uint32_t a;
    asm("{ .reg .u64 t; cvta.to.shared.u64 t, %1; cvt.u32.u64 %0, t; }" : "=r"(a) : "l"(p));
    return a;
}

__device__ __forceinline__ void ldmat_x4(uint32_t& r0, uint32_t& r1, uint32_t& r2, uint32_t& r3,
                                         uint32_t addr) {
    asm volatile("ldmatrix.sync.aligned.m8n8.x4.shared.b16 {%0,%1,%2,%3}, [%4];"
                 : "=r"(r0), "=r"(r1), "=r"(r2), "=r"(r3) : "r"(addr));
}

__device__ __forceinline__ void mma_16816(float& c0, float& c1, float& c2, float& c3,
                                          uint32_t a0, uint32_t a1, uint32_t a2, uint32_t a3,
                                          uint32_t b0, uint32_t b1) {
    asm volatile("mma.sync.aligned.m16n8k16.row.col.f32.f16.f16.f32 "
                 "{%0,%1,%2,%3}, {%4,%5,%6,%7}, {%8,%9}, {%0,%1,%2,%3};"
                 : "+f"(c0), "+f"(c1), "+f"(c2), "+f"(c3)
                 : "r"(a0), "r"(a1), "r"(a2), "r"(a3), "r"(b0), "r"(b1));
}

template <int K, int DO_BN, int DO_FILL>
__global__ __launch_bounds__(256, 2)
void mma_gemm_kernel(const float* __restrict__ A, const float* __restrict__ W,
                     __half2* __restrict__ C,
                     const float* __restrict__ gamma, const float* __restrict__ beta,
                     const int* __restrict__ src, const int* __restrict__ dst) {
    extern __shared__ char smem[];
    const int KS = K + 8;
    const int A_OFF = 512;
    const int B_OFF = A_OFF + 128 * KS * 2;
    float* s_scale = (float*)(smem + 0);
    float* s_shift = (float*)(smem + 256);
    __half* As = (__half*)(smem + A_OFF);
    __half* Bs = (__half*)(smem + B_OFF);

    int t = threadIdx.x;
    int wid = t >> 5;
    int lane = t & 31;
    int m0 = blockIdx.x * 128;

    if (DO_BN) {
        if (t < 64) {
            float m   = g_sum[0][t] * (1.0f / NN);
            float var = g_sq[0][t] * (1.0f / NN) - m * m;
            float sc  = gamma[t] * rsqrtf(var + BN_EPS);
            s_scale[t] = sc;
            s_shift[t] = beta[t] - m * sc;
        }
        __syncthreads();
    }

    // ---- A tile: fp32 -> (BN+ReLU) -> fp16 ----
    const int QK = K / 4;
    for (int idx = t; idx < 128 * QK; idx += 256) {
        int r = idx / QK;
        int q = idx - r * QK;
        int k = q * 4;
        int row = m0 + r;
        float4 v = make_float4(0.f, 0.f, 0.f, 0.f);
        if (row < NN) v = *reinterpret_cast<const float4*>(A + (size_t)row * K + k);
        if (DO_BN) {
            v.x = fmaxf(fmaf(v.x, s_scale[k + 0], s_shift[k + 0]), 0.f);
            v.y = fmaxf(fmaf(v.y, s_scale[k + 1], s_shift[k + 1]), 0.f);
            v.z = fmaxf(fmaf(v.z, s_scale[k + 2], s_shift[k + 2]), 0.f);
            v.w = fmaxf(fmaf(v.w, s_scale[k + 3], s_shift[k + 3]), 0.f);
        }
        __half2 h01 = __floats2half2_rn(v.x, v.y);
        __half2 h23 = __floats2half2_rn(v.z, v.w);
        ull pk = (ull)(*reinterpret_cast<uint32_t*>(&h01)) |
                 ((ull)(*reinterpret_cast<uint32_t*>(&h23)) << 32);
        *reinterpret_cast<ull*>(&As[r * KS + k]) = pk;
    }

    // ---- B tile = W^T: Bs[n][k] = W[k][n] ----
    for (int idx = t; idx < K * 64; idx += 256) {
        int k = idx >> 6;
        int n = idx & 63;
        Bs[n * KS + k] = __float2half_rn(W[idx]);
    }
    __syncthreads();

    float acc[8][4];
#pragma unroll
    for (int nb = 0; nb < 8; nb++)
#pragma unroll
        for (int j = 0; j < 4; j++) acc[nb][j] = 0.f;

    uint32_t as_base = smem_u32(As);
    uint32_t bs_base = smem_u32(Bs);

    uint32_t a_row = wid * 16 + (lane & 15);
    uint32_t a_addr0 = as_base + (a_row * KS + (lane >> 4) * 8) * 2;
    uint32_t b_n = (lane & 7) + ((lane >> 4) & 1) * 8;
    uint32_t b_k = ((lane >> 3) & 1) * 8;
    uint32_t b_addr0 = bs_base + (b_n * KS + b_k) * 2;

#pragma unroll
    for (int ks = 0; ks < K / 16; ks++) {
        uint32_t a0, a1, a2, a3;
        ldmat_x4(a0, a1, a2, a3, a_addr0 + ks * 32);
#pragma unroll
        for (int nb2 = 0; nb2 < 4; nb2++) {
            uint32_t b0, b1, b2, b3;
            ldmat_x4(b0, b1, b2, b3, b_addr0 + (nb2 * 16 * KS + ks * 16) * 2);
            mma_16816(acc[nb2 * 2 + 0][0], acc[nb2 * 2 + 0][1], acc[nb2 * 2 + 0][2], acc[nb2 * 2 + 0][3],
                      a0, a1, a2, a3, b0, b1);
            mma_16816(acc[nb2 * 2 + 1][0], acc[nb2 * 2 + 1][1], acc[nb2 * 2 + 1][2], acc[nb2 * 2 + 1][3],
                      a0, a1, a2, a3, b2, b3);
        }
    }

    int g = lane >> 2;
    int tq = lane & 3;
    int row0 = m0 + wid * 16 + g;
    int row1 = row0 + 8;
    if (row0 < NN) {
        float di = g_dinv[row0];
#pragma unroll
        for (int nb = 0; nb < 8; nb++)
            C[(size_t)row0 * 32 + nb * 4 + tq] = __floats2half2_rn(acc[nb][0] * di, acc[nb][1] * di);
    }
    if (row1 < NN) {
        float di = g_dinv[row1];
#pragma unroll
        for (int nb = 0; nb < 8; nb++)
            C[(size_t)row1 * 32 + nb * 4 + tq] = __floats2half2_rn(acc[nb][2] * di, acc[nb][3] * di);
    }

    // ---- fused CSR fill (independent; overlaps other blocks' MMA) ----
    if (DO_FILL) {
        int stride = gridDim.x * 256;
        for (int e = blockIdx.x * 256 + t; e < EE; e += stride)
            g_csr[g_off[dst[e]] + g_rank[e]] = src[e];
    }
}

// ---------------- aggregation (shfl-distributed fp16 gathers) + fused BN stats ----------------
__global__ void aggstats_kernel(const __half2* __restrict__ h, const float* __restrict__ bias,
                                float* __restrict__ out, int layer) {
    __shared__ float s_sum[64], s_sq[64];
    int t = threadIdx.x;
    if (t < 64) { s_sum[t] = 0.f; s_sq[t] = 0.f; }
    __syncthreads();
    int lane = t & 31;
    int warpId = blockIdx.x * (blockDim.x >> 5) + (t >> 5);
    int totalWarps = gridDim.x * (blockDim.x >> 5);
    float2 b = reinterpret_cast<const float2*>(bias)[lane];
    float sx = 0.f, sy = 0.f, sxx = 0.f, syy = 0.f;

    for (int i = warpId; i < NN; i += totalWarps) {
        float di = g_dinv[i];
        float2 acc = __half22float2(h[(size_t)i * 32 + lane]);  // self-loop (pre-scaled)
        int e0 = g_off[i], e1 = g_off[i + 1];
        for (int base = e0; base < e1; base += 32) {
            int m = min(32, e1 - base);
            // lane-parallel index load; indices then distributed via register shuffle,
            // so all row-gathers below are immediately issuable (MLP ~= deg)
            int sj = g_csr[base + ((lane < m) ? lane : 0)];
            int jj = 0;
            for (; jj + 3 < m; jj += 4) {
                int s0 = __shfl_sync(0xffffffffu, sj, jj);
                int s1 = __shfl_sync(0xffffffffu, sj, jj + 1);
                int s2 = __shfl_sync(0xffffffffu, sj, jj + 2);
                int s3 = __shfl_sync(0xffffffffu, sj, jj + 3);
                float2 v0 = __half22float2(h[(size_t)s0 * 32 + lane]);
                float2 v1 = __half22float2(h[(size_t)s1 * 32 + lane]);
                float2 v2 = __half22float2(h[(size_t)s2 * 32 + lane]);
                float2 v3 = __half22float2(h[(size_t)s3 * 32 + lane]);
                acc.x += (v0.x + v1.x) + (v2.x + v3.x);
                acc.y += (v0.y + v1.y) + (v2.y + v3.y);
            }
            for (; jj < m; jj++) {
                int s = __shfl_sync(0xffffffffu, sj, jj);
                float2 v = __half22float2(h[(size_t)s * 32 + lane]);
                acc.x += v.x; acc.y += v.y;
            }
        }
        float ox = fmaf(acc.x, di, b.x);
        float oy = fmaf(acc.y, di, b.y);
        reinterpret_cast<float2*>(out)[(size_t)i * 32 + lane] = make_float2(ox, oy);
        sx += ox; sxx += ox * ox;
        sy += oy; syy += oy * oy;
    }
    atomicAdd(&s_sum[lane * 2 + 0], sx);
    atomicAdd(&s_sq [lane * 2 + 0], sxx);
    atomicAdd(&s_sum[lane * 2 + 1], sy);
    atomicAdd(&s_sq [lane * 2 + 1], syy);
    __syncthreads();
    if (t < 64) {
        atomicAdd(&g_sum[layer][t], s_sum[t]);
        atomicAdd(&g_sq[layer][t], s_sq[t]);
    }
}

// BN apply with in-block prep: scale/shift from g_sum[1]/g_sq[1]
__global__ void bnapply_kernel(const float* __restrict__ v,
                               const float* __restrict__ gamma, const float* __restrict__ beta,
                               float* __restrict__ out) {
    __shared__ float sc[64], sf[64];
    int t = threadIdx.x;
    if (t < 64) {
        float m   = g_sum[1][t] * (1.0f / NN);
        float var = g_sq[1][t] * (1.0f / NN) - m * m;
        float s   = gamma[t] * rsqrtf(var + BN_EPS);
        sc[t] = s;
        sf[t] = beta[t] - m * s;
    }
    __syncthreads();
    int idx = blockIdx.x * blockDim.x + t;
    if (idx >= NN * 16) return;
    float4 x = reinterpret_cast<const float4*>(v)[idx];
    int c = (idx & 15) * 4;
    x.x = fmaxf(fmaf(x.x, sc[c + 0], sf[c + 0]), 0.f);
    x.y = fmaxf(fmaf(x.y, sc[c + 1], sf[c + 1]), 0.f);
    x.z = fmaxf(fmaf(x.z, sc[c + 2], sf[c + 2]), 0.f);
    x.w = fmaxf(fmaf(x.w, sc[c + 3], sf[c + 3]), 0.f);
    reinterpret_cast<float4*>(out)[idx] = x;
}

// ---------------- launch ----------------
extern "C" void kernel_launch(void* const* d_in, const int* in_sizes, int n_in,
                              void* d_out, int out_size) {
    const float* x   = (const float*)d_in[0];
    const int*   ei  = (const int*)d_in[1];
    const float* W1  = (const float*)d_in[2];
    const float* b1  = (const float*)d_in[3];
    const float* g1  = (const float*)d_in[4];
    const float* bt1 = (const float*)d_in[5];
    const float* W2  = (const float*)d_in[6];
    const float* b2  = (const float*)d_in[7];
    const float* g2  = (const float*)d_in[8];
    const float* bt2 = (const float*)d_in[9];
    float* out = (float*)d_out;

    const int* src = ei;
    const int* dst = ei + EE;

    __half2* hP = nullptr;
    float* aggP = nullptr;
    cudaGetSymbolAddress((void**)&hP, g_h);
    cudaGetSymbolAddress((void**)&aggP, g_agg);

    const int NB = (NN + 1023) / 1024;  // 98
    const int AGG_BLOCKS = 1184;
    const int SMEM1 = 512 + 128 * (INF + 8) * 2 + 64 * (INF + 8) * 2;  // 52736
    const int SMEM2 = 512 + 128 * (HH + 8) * 2 + 64 * (HH + 8) * 2;    // 28160

    cudaFuncSetAttribute(mma_gemm_kernel<INF, 0, 1>,
                         cudaFuncAttributeMaxDynamicSharedMemorySize, SMEM1);
    cudaFuncSetAttribute(mma_gemm_kernel<HH, 1, 0>,
                         cudaFuncAttributeMaxDynamicSharedMemorySize, SMEM2);

    hist_kernel<<<(EE + 255) / 256, 256>>>(dst);
    degscan_kernel<<<NB, 1024>>>(NB);

    // ---- layer 1 (CSR fill fused into GEMM1) ----
    mma_gemm_kernel<INF, 0, 1><<<(NN + 127) / 128, 256, SMEM1>>>(x, W1, hP, nullptr, nullptr, src, dst);
    aggstats_kernel<<<AGG_BLOCKS, 256>>>(hP, b1, aggP, 0);

    // ---- layer 2: BN(layer1)+ReLU fused into A-tile load ----
    mma_gemm_kernel<HH, 1, 0><<<(NN + 127) / 128, 256, SMEM2>>>(aggP, W2, hP, g1, bt1, nullptr, nullptr);
    aggstats_kernel<<<AGG_BLOCKS, 256>>>(hP, b2, aggP, 1);
    bnapply_kernel<<<(NN * 16 + 255) / 256, 256>>>(aggP, g2, bt2, out);
}

// round 10
// speedup vs baseline: 1.0687x; 1.0687x over previous
#include <cuda_runtime.h>
#include <cuda_bf16.h>
#include <cuda_fp16.h>
#include <math.h>
#include <stdint.h>

#define NN 100000
#define EE 1000000
#define INF 128
#define HH 64
#define BN_EPS 1e-5f

typedef unsigned long long ull;

// ---------------- scratch (device globals, no runtime alloc) ----------------
// Invariant: g_indeg is all-zero at every kernel_launch entry (zero-initialized at
// module load; degscan re-zeros it after use on every execution).
__device__ int   g_indeg[NN];
__device__ int   g_off[NN + 1];
__device__ int   g_rank[EE];
__device__ int   g_csr[EE];
__device__ float g_dinv[NN];
__device__ int   g_bsum[128];
__device__ int   g_boff[128];
__device__ int   g_ticket;
__device__ int   g_flag;
__device__ float g_sum[2][HH];
__device__ float g_sq[2][HH];

__device__ __half2 g_h[(size_t)NN * 32];   // GEMM output (fp16 pairs), pre-scaled by dinv[row]
__device__ float   g_agg[(size_t)NN * HH]; // aggregation output (pre-BN, fp32)

// ---------------- graph build ----------------

// histogram + per-edge rank; also resets per-call scalars/stats (indeg is pre-zeroed)
__global__ void hist_kernel(const int* __restrict__ dst) {
    int e = blockIdx.x * blockDim.x + threadIdx.x;
    if (e < EE) g_rank[e] = atomicAdd(&g_indeg[dst[e]], 1);
    if (e == 0) { g_ticket = 0; g_flag = 0; }
    if (e < 2 * HH) {
        ((float*)g_sum)[e] = 0.f;
        ((float*)g_sq)[e]  = 0.f;
    }
}

// fused: per-block inclusive scan + cross-block scan (last-block election) + finalize
// + self-clean (re-zero indeg). 98 blocks, all resident -> flag spin is safe.
__global__ void degscan_kernel(int nb) {
    __shared__ int sh[1024];
    __shared__ int amLast;
    int t = threadIdx.x;
    int b = blockIdx.x;
    int idx = b * 1024 + t;
    int v = (idx < NN) ? g_indeg[idx] : 0;
    sh[t] = v;
    __syncthreads();
    for (int o = 1; o < 1024; o <<= 1) {
        int a = (t >= o) ? sh[t - o] : 0;
        __syncthreads();
        sh[t] += a;
        __syncthreads();
    }
    int incl = sh[t];
    if (t == 1023) {
        g_bsum[b] = incl;
        __threadfence();
        amLast = (atomicAdd(&g_ticket, 1) == gridDim.x - 1);
    }
    __syncthreads();
    if (amLast) {
        int bv = (t < nb) ? g_bsum[t] : 0;
        sh[t] = (t < 128) ? bv : 0;
        __syncthreads();
        for (int o = 1; o < 128; o <<= 1) {
            int a = (t >= o && t < 128) ? sh[t - o] : 0;
            __syncthreads();
            if (t < 128) sh[t] += a;
            __syncthreads();
        }
        if (t < nb) g_boff[t] = sh[t] - bv;
        if (t == nb - 1) g_off[NN] = sh[t];
        __threadfence();
        if (t == 0) atomicExch(&g_flag, 1);
    }
    if (t == 0) {
        while (atomicAdd(&g_flag, 0) == 0) {}
    }
    __syncthreads();
    if (idx < NN) {
        int off = g_boff[b] + incl - v;
        g_off[idx] = off;
        g_dinv[idx] = rsqrtf((float)(v + 1));   // deg = indeg + self-loop
        g_indeg[idx] = 0;                        // self-clean for next call
    }
}

// ---------------- HMMA GEMM (mma.sync m16n8k16, fp16 in / fp32 accum) ----------------

__device__ __forceinline__ uint32_t smem_u32(const void* p) {
    uint32_t a;
    asm("{ .reg .u64 t; cvta.to.shared.u64 t, %1; cvt.u32.u64 %0, t; }" : "=r"(a) : "l"(p));
    return a;
}

__device__ __forceinline__ void ldmat_x4(uint32_t& r0, uint32_t& r1, uint32_t& r2, uint32_t& r3,
                                         uint32_t addr) {
    asm volatile("ldmatrix.sync.aligned.m8n8.x4.shared.b16 {%0,%1,%2,%3}, [%4];"
                 : "=r"(r0), "=r"(r1), "=r"(r2), "=r"(r3) : "r"(addr));
}

__device__ __forceinline__ void mma_16816(float& c0, float& c1, float& c2, float& c3,
                                          uint32_t a0, uint32_t a1, uint32_t a2, uint32_t a3,
                                          uint32_t b0, uint32_t b1) {
    asm volatile("mma.sync.aligned.m16n8k16.row.col.f32.f16.f16.f32 "
                 "{%0,%1,%2,%3}, {%4,%5,%6,%7}, {%8,%9}, {%0,%1,%2,%3};"
                 : "+f"(c0), "+f"(c1), "+f"(c2), "+f"(c3)
                 : "r"(a0), "r"(a1), "r"(a2), "r"(a3), "r"(b0), "r"(b1));
}

template <int K, int DO_BN, int DO_FILL>
__global__ __launch_bounds__(256, 2)
void mma_gemm_kernel(const float* __restrict__ A, const float* __restrict__ W,
                     __half2* __restrict__ C,
                     const float* __restrict__ gamma, const float* __restrict__ beta,
                     const int* __restrict__ src, const int* __restrict__ dst) {
    extern __shared__ char smem[];
    const int KS = K + 8;
    const int A_OFF = 512;
    const int B_OFF = A_OFF + 128 * KS * 2;
    float* s_scale = (float*)(smem + 0);
    float* s_shift = (float*)(smem + 256);
    __half* As = (__half*)(smem + A_OFF);
    __half* Bs = (__half*)(smem + B_OFF);

    int t = threadIdx.x;
    int wid = t >> 5;
    int lane = t & 31;
    int m0 = blockIdx.x * 128;

    if (DO_BN) {
        if (t < 64) {
            float m   = g_sum[0][t] * (1.0f / NN);
            float var = g_sq[0][t] * (1.0f / NN) - m * m;
            float sc  = gamma[t] * rsqrtf(var + BN_EPS);
            s_scale[t] = sc;
            s_shift[t] = beta[t] - m * sc;
        }
        __syncthreads();
    }

    // ---- A tile: fp32 -> (BN+ReLU) -> fp16 ----
    const int QK = K / 4;
    for (int idx = t; idx < 128 * QK; idx += 256) {
        int r = idx / QK;
        int q = idx - r * QK;
        int k = q * 4;
        int row = m0 + r;
        float4 v = make_float4(0.f, 0.f, 0.f, 0.f);
        if (row < NN) v = *reinterpret_cast<const float4*>(A + (size_t)row * K + k);
        if (DO_BN) {
            v.x = fmaxf(fmaf(v.x, s_scale[k + 0], s_shift[k + 0]), 0.f);
            v.y = fmaxf(fmaf(v.y, s_scale[k + 1], s_shift[k + 1]), 0.f);
            v.z = fmaxf(fmaf(v.z, s_scale[k + 2], s_shift[k + 2]), 0.f);
            v.w = fmaxf(fmaf(v.w, s_scale[k + 3], s_shift[k + 3]), 0.f);
        }
        __half2 h01 = __floats2half2_rn(v.x, v.y);
        __half2 h23 = __floats2half2_rn(v.z, v.w);
        ull pk = (ull)(*reinterpret_cast<uint32_t*>(&h01)) |
                 ((ull)(*reinterpret_cast<uint32_t*>(&h23)) << 32);
        *reinterpret_cast<ull*>(&As[r * KS + k]) = pk;
    }

    // ---- B tile = W^T: Bs[n][k] = W[k][n] ----
    for (int idx = t; idx < K * 64; idx += 256) {
        int k = idx >> 6;
        int n = idx & 63;
        Bs[n * KS + k] = __float2half_rn(W[idx]);
    }
    __syncthreads();

    float acc[8][4];
#pragma unroll
    for (int nb = 0; nb < 8; nb++)
#pragma unroll
        for (int j = 0; j < 4; j++) acc[nb][j] = 0.f;

    uint32_t as_base = smem_u32(As);
    uint32_t bs_base = smem_u32(Bs);

    uint32_t a_row = wid * 16 + (lane & 15);
    uint32_t a_addr0 = as_base + (a_row * KS + (lane >> 4) * 8) * 2;
    uint32_t b_n = (lane & 7) + ((lane >> 4) & 1) * 8;
    uint32_t b_k = ((lane >> 3) & 1) * 8;
    uint32_t b_addr0 = bs_base + (b_n * KS + b_k) * 2;

#pragma unroll
    for (int ks = 0; ks < K / 16; ks++) {
        uint32_t a0, a1, a2, a3;
        ldmat_x4(a0, a1, a2, a3, a_addr0 + ks * 32);
#pragma unroll
        for (int nb2 = 0; nb2 < 4; nb2++) {
            uint32_t b0, b1, b2, b3;
            ldmat_x4(b0, b1, b2, b3, b_addr0 + (nb2 * 16 * KS + ks * 16) * 2);
            mma_16816(acc[nb2 * 2 + 0][0], acc[nb2 * 2 + 0][1], acc[nb2 * 2 + 0][2], acc[nb2 * 2 + 0][3],
                      a0, a1, a2, a3, b0, b1);
            mma_16816(acc[nb2 * 2 + 1][0], acc[nb2 * 2 + 1][1], acc[nb2 * 2 + 1][2], acc[nb2 * 2 + 1][3],
                      a0, a1, a2, a3, b2, b3);
        }
    }

    int g = lane >> 2;
    int tq = lane & 3;
    int row0 = m0 + wid * 16 + g;
    int row1 = row0 + 8;
    if (row0 < NN) {
        float di = g_dinv[row0];
#pragma unroll
        for (int nb = 0; nb < 8; nb++)
            C[(size_t)row0 * 32 + nb * 4 + tq] = __floats2half2_rn(acc[nb][0] * di, acc[nb][1] * di);
    }
    if (row1 < NN) {
        float di = g_dinv[row1];
#pragma unroll
        for (int nb = 0; nb < 8; nb++)
            C[(size_t)row1 * 32 + nb * 4 + tq] = __floats2half2_rn(acc[nb][2] * di, acc[nb][3] * di);
    }

    // ---- fused CSR fill (independent; overlaps other blocks' MMA) ----
    if (DO_FILL) {
        int stride = gridDim.x * 256;
        for (int e = blockIdx.x * 256 + t; e < EE; e += stride)
            g_csr[g_off[dst[e]] + g_rank[e]] = src[e];
    }
}

// ---------------- aggregation (fp16 gather, fp32 accum) + fused BN statistics ----------------
// __launch_bounds__(256, 8): forces regs<=32 so 8 blocks/SM are resident (64 warps,
// full occupancy) — agg is issue/latency bound, not L2 bound (measured L2=14.4%).
__global__ __launch_bounds__(256, 8)
void aggstats_kernel(const __half2* __restrict__ h, const float* __restrict__ bias,
                     float* __restrict__ out, int layer) {
    __shared__ float s_sum[64], s_sq[64];
    int t = threadIdx.x;
    if (t < 64) { s_sum[t] = 0.f; s_sq[t] = 0.f; }
    __syncthreads();
    int lane = t & 31;
    int warpId = blockIdx.x * (blockDim.x >> 5) + (t >> 5);
    int totalWarps = gridDim.x * (blockDim.x >> 5);
    float2 b = reinterpret_cast<const float2*>(bias)[lane];
    float sx = 0.f, sy = 0.f, sxx = 0.f, syy = 0.f;

    for (int i = warpId; i < NN; i += totalWarps) {
        float di = g_dinv[i];
        float2 acc = __half22float2(h[(size_t)i * 32 + lane]);  // self-loop (pre-scaled)
        int e0 = g_off[i], e1 = g_off[i + 1];
        int j = e0;
        for (; j + 3 < e1; j += 4) {
            int s0 = g_csr[j], s1 = g_csr[j + 1], s2 = g_csr[j + 2], s3 = g_csr[j + 3];
            float2 v0 = __half22float2(h[(size_t)s0 * 32 + lane]);
            float2 v1 = __half22float2(h[(size_t)s1 * 32 + lane]);
            float2 v2 = __half22float2(h[(size_t)s2 * 32 + lane]);
            float2 v3 = __half22float2(h[(size_t)s3 * 32 + lane]);
            acc.x += (v0.x + v1.x) + (v2.x + v3.x);
            acc.y += (v0.y + v1.y) + (v2.y + v3.y);
        }
        for (; j < e1; j++) {
            float2 v = __half22float2(h[(size_t)g_csr[j] * 32 + lane]);
            acc.x += v.x; acc.y += v.y;
        }
        float ox = fmaf(acc.x, di, b.x);
        float oy = fmaf(acc.y, di, b.y);
        reinterpret_cast<float2*>(out)[(size_t)i * 32 + lane] = make_float2(ox, oy);
        sx += ox; sxx += ox * ox;
        sy += oy; syy += oy * oy;
    }
    atomicAdd(&s_sum[lane * 2 + 0], sx);
    atomicAdd(&s_sq [lane * 2 + 0], sxx);
    atomicAdd(&s_sum[lane * 2 + 1], sy);
    atomicAdd(&s_sq [lane * 2 + 1], syy);
    __syncthreads();
    if (t < 64) {
        atomicAdd(&g_sum[layer][t], s_sum[t]);
        atomicAdd(&g_sq[layer][t], s_sq[t]);
    }
}

// BN apply with in-block prep: scale/shift from g_sum[1]/g_sq[1]
__global__ void bnapply_kernel(const float* __restrict__ v,
                               const float* __restrict__ gamma, const float* __restrict__ beta,
                               float* __restrict__ out) {
    __shared__ float sc[64], sf[64];
    int t = threadIdx.x;
    if (t < 64) {
        float m   = g_sum[1][t] * (1.0f / NN);
        float var = g_sq[1][t] * (1.0f / NN) - m * m;
        float s   = gamma[t] * rsqrtf(var + BN_EPS);
        sc[t] = s;
        sf[t] = beta[t] - m * s;
    }
    __syncthreads();
    int idx = blockIdx.x * blockDim.x + t;
    if (idx >= NN * 16) return;
    float4 x = reinterpret_cast<const float4*>(v)[idx];
    int c = (idx & 15) * 4;
    x.x = fmaxf(fmaf(x.x, sc[c + 0], sf[c + 0]), 0.f);
    x.y = fmaxf(fmaf(x.y, sc[c + 1], sf[c + 1]), 0.f);
    x.z = fmaxf(fmaf(x.z, sc[c + 2], sf[c + 2]), 0.f);
    x.w = fmaxf(fmaf(x.w, sc[c + 3], sf[c + 3]), 0.f);
    reinterpret_cast<float4*>(out)[idx] = x;
}

// ---------------- launch ----------------
extern "C" void kernel_launch(void* const* d_in, const int* in_sizes, int n_in,
                              void* d_out, int out_size) {
    const float* x   = (const float*)d_in[0];
    const int*   ei  = (const int*)d_in[1];
    const float* W1  = (const float*)d_in[2];
    const float* b1  = (const float*)d_in[3];
    const float* g1  = (const float*)d_in[4];
    const float* bt1 = (const float*)d_in[5];
    const float* W2  = (const float*)d_in[6];
    const float* b2  = (const float*)d_in[7];
    const float* g2  = (const float*)d_in[8];
    const float* bt2 = (const float*)d_in[9];
    float* out = (float*)d_out;

    const int* src = ei;
    const int* dst = ei + EE;

    __half2* hP = nullptr;
    float* aggP = nullptr;
    cudaGetSymbolAddress((void**)&hP, g_h);
    cudaGetSymbolAddress((void**)&aggP, g_agg);

    const int NB = (NN + 1023) / 1024;  // 98
    const int AGG_BLOCKS = 1184;        // 148 SMs * 8 resident blocks (one full wave)
    const int SMEM1 = 512 + 128 * (INF + 8) * 2 + 64 * (INF + 8) * 2;  // 52736
    const int SMEM2 = 512 + 128 * (HH + 8) * 2 + 64 * (HH + 8) * 2;    // 28160

    cudaFuncSetAttribute(mma_gemm_kernel<INF, 0, 1>,
                         cudaFuncAttributeMaxDynamicSharedMemorySize, SMEM1);
    cudaFuncSetAttribute(mma_gemm_kernel<HH, 1, 0>,
                         cudaFuncAttributeMaxDynamicSharedMemorySize, SMEM2);

    hist_kernel<<<(EE + 255) / 256, 256>>>(dst);
    degscan_kernel<<<NB, 1024>>>(NB);

    // ---- layer 1 (CSR fill fused into GEMM1) ----
    mma_gemm_kernel<INF, 0, 1><<<(NN + 127) / 128, 256, SMEM1>>>(x, W1, hP, nullptr, nullptr, src, dst);
    aggstats_kernel<<<AGG_BLOCKS, 256>>>(hP, b1, aggP, 0);

    // ---- layer 2: BN(layer1)+ReLU fused into A-tile load ----
    mma_gemm_kernel<HH, 1, 0><<<(NN + 127) / 128, 256, SMEM2>>>(aggP, W2, hP, g1, bt1, nullptr, nullptr);
    aggstats_kernel<<<AGG_BLOCKS, 256>>>(hP, b2, aggP, 1);
    bnapply_kernel<<<(NN * 16 + 255) / 256, 256>>>(aggP, g2, bt2, out);
}

// round 11
// speedup vs baseline: 1.1078x; 1.0367x over previous
#include <cuda_runtime.h>
#include <cuda_bf16.h>
#include <cuda_fp16.h>
#include <math.h>
#include <stdint.h>

#define NN 100000
#define EE 1000000
#define INF 128
#define HH 64
#define BN_EPS 1e-5f

typedef unsigned long long ull;

// ---------------- scratch (device globals, no runtime alloc) ----------------
// Invariant: g_indeg is all-zero at every kernel_launch entry (zero-initialized at
// module load; degscan re-zeros it after use on every execution).
__device__ int   g_indeg[NN];
__device__ int   g_off[NN + 1];
__device__ int   g_rank[EE];
__device__ int   g_csr[EE];
__device__ float g_dinv[NN];
__device__ int   g_bsum[128];
__device__ int   g_boff[128];
__device__ int   g_ticket;
__device__ int   g_flag;
__device__ float g_sum[2][HH];
__device__ float g_sq[2][HH];

__device__ __half2 g_h[(size_t)NN * 32];   // GEMM output (fp16 pairs), pre-scaled by dinv[row]
__device__ float   g_agg[(size_t)NN * HH]; // aggregation output (pre-BN, fp32)

// ---------------- graph build ----------------

// histogram + per-edge rank; also resets per-call scalars/stats (indeg is pre-zeroed)
__global__ void hist_kernel(const int* __restrict__ dst) {
    int e = blockIdx.x * blockDim.x + threadIdx.x;
    if (e < EE) g_rank[e] = atomicAdd(&g_indeg[dst[e]], 1);
    if (e == 0) { g_ticket = 0; g_flag = 0; }
    if (e < 2 * HH) {
        ((float*)g_sum)[e] = 0.f;
        ((float*)g_sq)[e]  = 0.f;
    }
}

// fused: per-block inclusive scan + cross-block scan (last-block election) + finalize
// + self-clean (re-zero indeg). 98 blocks, all resident -> flag spin is safe.
__global__ void degscan_kernel(int nb) {
    __shared__ int sh[1024];
    __shared__ int amLast;
    int t = threadIdx.x;
    int b = blockIdx.x;
    int idx = b * 1024 + t;
    int v = (idx < NN) ? g_indeg[idx] : 0;
    sh[t] = v;
    __syncthreads();
    for (int o = 1; o < 1024; o <<= 1) {
        int a = (t >= o) ? sh[t - o] : 0;
        __syncthreads();
        sh[t] += a;
        __syncthreads();
    }
    int incl = sh[t];
    if (t == 1023) {
        g_bsum[b] = incl;
        __threadfence();
        amLast = (atomicAdd(&g_ticket, 1) == gridDim.x - 1);
    }
    __syncthreads();
    if (amLast) {
        int bv = (t < nb) ? g_bsum[t] : 0;
        sh[t] = (t < 128) ? bv : 0;
        __syncthreads();
        for (int o = 1; o < 128; o <<= 1) {
            int a = (t >= o && t < 128) ? sh[t - o] : 0;
            __syncthreads();
            if (t < 128) sh[t] += a;
            __syncthreads();
        }
        if (t < nb) g_boff[t] = sh[t] - bv;
        if (t == nb - 1) g_off[NN] = sh[t];
        __threadfence();
        if (t == 0) atomicExch(&g_flag, 1);
    }
    if (t == 0) {
        while (atomicAdd(&g_flag, 0) == 0) {}
    }
    __syncthreads();
    if (idx < NN) {
        int off = g_boff[b] + incl - v;
        g_off[idx] = off;
        g_dinv[idx] = rsqrtf((float)(v + 1));   // deg = indeg + self-loop
        g_indeg[idx] = 0;                        // self-clean for next call
    }
}

// ---------------- HMMA GEMM (mma.sync m16n8k16, fp16 in / fp32 accum) ----------------

__device__ __forceinline__ uint32_t smem_u32(const void* p) {
    uint32_t a;
    asm("{ .reg .u64 t; cvta.to.shared.u64 t, %1; cvt.u32.u64 %0, t; }" : "=r"(a) : "l"(p));
    return a;
}

__device__ __forceinline__ void ldmat_x4(uint32_t& r0, uint32_t& r1, uint32_t& r2, uint32_t& r3,
                                         uint32_t addr) {
    asm volatile("ldmatrix.sync.aligned.m8n8.x4.shared.b16 {%0,%1,%2,%3}, [%4];"
                 : "=r"(r0), "=r"(r1), "=r"(r2), "=r"(r3) : "r"(addr));
}

__device__ __forceinline__ void mma_16816(float& c0, float& c1, float& c2, float& c3,
                                          uint32_t a0, uint32_t a1, uint32_t a2, uint32_t a3,
                                          uint32_t b0, uint32_t b1) {
    asm volatile("mma.sync.aligned.m16n8k16.row.col.f32.f16.f16.f32 "
                 "{%0,%1,%2,%3}, {%4,%5,%6,%7}, {%8,%9}, {%0,%1,%2,%3};"
                 : "+f"(c0), "+f"(c1), "+f"(c2), "+f"(c3)
                 : "r"(a0), "r"(a1), "r"(a2), "r"(a3), "r"(b0), "r"(b1));
}

template <int K, int DO_BN, int DO_FILL>
__global__ __launch_bounds__(256, 2)
void mma_gemm_kernel(const float* __restrict__ A, const float* __restrict__ W,
                     __half2* __restrict__ C,
                     const float* __restrict__ gamma, const float* __restrict__ beta,
                     const int* __restrict__ src, const int* __restrict__ dst) {
    extern __shared__ char smem[];
    const int KS = K + 8;
    const int A_OFF = 512;
    const int B_OFF = A_OFF + 128 * KS * 2;
    float* s_scale = (float*)(smem + 0);
    float* s_shift = (float*)(smem + 256);
    __half* As = (__half*)(smem + A_OFF);
    __half* Bs = (__half*)(smem + B_OFF);

    int t = threadIdx.x;
    int wid = t >> 5;
    int lane = t & 31;
    int m0 = blockIdx.x * 128;

    if (DO_BN) {
        if (t < 64) {
            float m   = g_sum[0][t] * (1.0f / NN);
            float var = g_sq[0][t] * (1.0f / NN) - m * m;
            float sc  = gamma[t] * rsqrtf(var + BN_EPS);
            s_scale[t] = sc;
            s_shift[t] = beta[t] - m * sc;
        }
        __syncthreads();
    }

    // ---- A tile: fp32 -> (BN+ReLU) -> fp16 ----
    const int QK = K / 4;
    for (int idx = t; idx < 128 * QK; idx += 256) {
        int r = idx / QK;
        int q = idx - r * QK;
        int k = q * 4;
        int row = m0 + r;
        float4 v = make_float4(0.f, 0.f, 0.f, 0.f);
        if (row < NN) v = *reinterpret_cast<const float4*>(A + (size_t)row * K + k);
        if (DO_BN) {
            v.x = fmaxf(fmaf(v.x, s_scale[k + 0], s_shift[k + 0]), 0.f);
            v.y = fmaxf(fmaf(v.y, s_scale[k + 1], s_shift[k + 1]), 0.f);
            v.z = fmaxf(fmaf(v.z, s_scale[k + 2], s_shift[k + 2]), 0.f);
            v.w = fmaxf(fmaf(v.w, s_scale[k + 3], s_shift[k + 3]), 0.f);
        }
        __half2 h01 = __floats2half2_rn(v.x, v.y);
        __half2 h23 = __floats2half2_rn(v.z, v.w);
        ull pk = (ull)(*reinterpret_cast<uint32_t*>(&h01)) |
                 ((ull)(*reinterpret_cast<uint32_t*>(&h23)) << 32);
        *reinterpret_cast<ull*>(&As[r * KS + k]) = pk;
    }

    // ---- B tile = W^T: Bs[n][k] = W[k][n] ----
    for (int idx = t; idx < K * 64; idx += 256) {
        int k = idx >> 6;
        int n = idx & 63;
        Bs[n * KS + k] = __float2half_rn(W[idx]);
    }
    __syncthreads();

    float acc[8][4];
#pragma unroll
    for (int nb = 0; nb < 8; nb++)
#pragma unroll
        for (int j = 0; j < 4; j++) acc[nb][j] = 0.f;

    uint32_t as_base = smem_u32(As);
    uint32_t bs_base = smem_u32(Bs);

    uint32_t a_row = wid * 16 + (lane & 15);
    uint32_t a_addr0 = as_base + (a_row * KS + (lane >> 4) * 8) * 2;
    uint32_t b_n = (lane & 7) + ((lane >> 4) & 1) * 8;
    uint32_t b_k = ((lane >> 3) & 1) * 8;
    uint32_t b_addr0 = bs_base + (b_n * KS + b_k) * 2;

#pragma unroll
    for (int ks = 0; ks < K / 16; ks++) {
        uint32_t a0, a1, a2, a3;
        ldmat_x4(a0, a1, a2, a3, a_addr0 + ks * 32);
#pragma unroll
        for (int nb2 = 0; nb2 < 4; nb2++) {
            uint32_t b0, b1, b2, b3;
            ldmat_x4(b0, b1, b2, b3, b_addr0 + (nb2 * 16 * KS + ks * 16) * 2);
            mma_16816(acc[nb2 * 2 + 0][0], acc[nb2 * 2 + 0][1], acc[nb2 * 2 + 0][2], acc[nb2 * 2 + 0][3],
                      a0, a1, a2, a3, b0, b1);
            mma_16816(acc[nb2 * 2 + 1][0], acc[nb2 * 2 + 1][1], acc[nb2 * 2 + 1][2], acc[nb2 * 2 + 1][3],
                      a0, a1, a2, a3, b2, b3);
        }
    }

    int g = lane >> 2;
    int tq = lane & 3;
    int row0 = m0 + wid * 16 + g;
    int row1 = row0 + 8;
    if (row0 < NN) {
        float di = g_dinv[row0];
#pragma unroll
        for (int nb = 0; nb < 8; nb++)
            C[(size_t)row0 * 32 + nb * 4 + tq] = __floats2half2_rn(acc[nb][0] * di, acc[nb][1] * di);
    }
    if (row1 < NN) {
        float di = g_dinv[row1];
#pragma unroll
        for (int nb = 0; nb < 8; nb++)
            C[(size_t)row1 * 32 + nb * 4 + tq] = __floats2half2_rn(acc[nb][2] * di, acc[nb][3] * di);
    }

    // ---- fused CSR fill (independent; overlaps other blocks' MMA) ----
    if (DO_FILL) {
        int stride = gridDim.x * 256;
        for (int e = blockIdx.x * 256 + t; e < EE; e += stride)
            g_csr[g_off[dst[e]] + g_rank[e]] = src[e];
    }
}

// ---------------- aggregation + fused BN statistics ----------------
// 2 edges per warp memory-iteration: lanes 0-15 gather even edges, 16-31 odd edges,
// each lane loading uint2 (4 channels, 8B) so 16 lanes cover a full 128B row.
// Half-warp partial sums combined via shfl; lanes 0-15 write + accumulate stats.
__global__ __launch_bounds__(256, 6)
void aggstats_kernel(const __half2* __restrict__ h, const float* __restrict__ bias,
                     float* __restrict__ out, int layer) {
    __shared__ float s_sum[64], s_sq[64];
    int t = threadIdx.x;
    if (t < 64) { s_sum[t] = 0.f; s_sq[t] = 0.f; }
    __syncthreads();
    int lane = t & 31;
    int c4 = lane & 15;          // uint2 slot: channels 4*c4 .. 4*c4+3
    int hw = lane >> 4;          // 0: even edges, 1: odd edges
    int warpId = blockIdx.x * (blockDim.x >> 5) + (t >> 5);
    int totalWarps = gridDim.x * (blockDim.x >> 5);
    const uint2* h4 = reinterpret_cast<const uint2*>(h);  // 16 uint2 per row
    float4 b4 = reinterpret_cast<const float4*>(bias)[c4];
    float sm0 = 0.f, sm1 = 0.f, sm2 = 0.f, sm3 = 0.f;
    float sq0 = 0.f, sq1 = 0.f, sq2 = 0.f, sq3 = 0.f;

    for (int i = warpId; i < NN; i += totalWarps) {
        float di = g_dinv[i];
        float4 acc;
        if (hw == 0) {  // self-loop (pre-scaled) seeds the even half
            uint2 sv = h4[(unsigned)i * 16u + c4];
            float2 a0 = __half22float2(*reinterpret_cast<__half2*>(&sv.x));
            float2 a1 = __half22float2(*reinterpret_cast<__half2*>(&sv.y));
            acc = make_float4(a0.x, a0.y, a1.x, a1.y);
        } else {
            acc = make_float4(0.f, 0.f, 0.f, 0.f);
        }
        int e0 = g_off[i], e1 = g_off[i + 1];
        int j = e0 + hw;
        for (; j + 6 < e1; j += 8) {
            int s0 = g_csr[j], s1 = g_csr[j + 2], s2 = g_csr[j + 4], s3 = g_csr[j + 6];
            uint2 v0 = h4[(unsigned)s0 * 16u + c4];
            uint2 v1 = h4[(unsigned)s1 * 16u + c4];
            uint2 v2 = h4[(unsigned)s2 * 16u + c4];
            uint2 v3 = h4[(unsigned)s3 * 16u + c4];
            float2 p0 = __half22float2(*reinterpret_cast<__half2*>(&v0.x));
            float2 p1 = __half22float2(*reinterpret_cast<__half2*>(&v0.y));
            float2 q0 = __half22float2(*reinterpret_cast<__half2*>(&v1.x));
            float2 q1 = __half22float2(*reinterpret_cast<__half2*>(&v1.y));
            float2 r0 = __half22float2(*reinterpret_cast<__half2*>(&v2.x));
            float2 r1 = __half22float2(*reinterpret_cast<__half2*>(&v2.y));
            float2 w0 = __half22float2(*reinterpret_cast<__half2*>(&v3.x));
            float2 w1 = __half22float2(*reinterpret_cast<__half2*>(&v3.y));
            acc.x += (p0.x + q0.x) + (r0.x + w0.x);
            acc.y += (p0.y + q0.y) + (r0.y + w0.y);
            acc.z += (p1.x + q1.x) + (r1.x + w1.x);
            acc.w += (p1.y + q1.y) + (r1.y + w1.y);
        }
        for (; j < e1; j += 2) {
            uint2 v = h4[(unsigned)g_csr[j] * 16u + c4];
            float2 p0 = __half22float2(*reinterpret_cast<__half2*>(&v.x));
            float2 p1 = __half22float2(*reinterpret_cast<__half2*>(&v.y));
            acc.x += p0.x; acc.y += p0.y; acc.z += p1.x; acc.w += p1.y;
        }
        // combine odd half into even half
        acc.x += __shfl_down_sync(0xffffffffu, acc.x, 16);
        acc.y += __shfl_down_sync(0xffffffffu, acc.y, 16);
        acc.z += __shfl_down_sync(0xffffffffu, acc.z, 16);
        acc.w += __shfl_down_sync(0xffffffffu, acc.w, 16);
        if (hw == 0) {
            float4 o;
            o.x = fmaf(acc.x, di, b4.x);
            o.y = fmaf(acc.y, di, b4.y);
            o.z = fmaf(acc.z, di, b4.z);
            o.w = fmaf(acc.w, di, b4.w);
            reinterpret_cast<float4*>(out)[(unsigned)i * 16u + c4] = o;
            sm0 += o.x; sq0 += o.x * o.x;
            sm1 += o.y; sq1 += o.y * o.y;
            sm2 += o.z; sq2 += o.z * o.z;
            sm3 += o.w; sq3 += o.w * o.w;
        }
    }
    if (hw == 0) {
        atomicAdd(&s_sum[c4 * 4 + 0], sm0);
        atomicAdd(&s_sum[c4 * 4 + 1], sm1);
        atomicAdd(&s_sum[c4 * 4 + 2], sm2);
        atomicAdd(&s_sum[c4 * 4 + 3], sm3);
        atomicAdd(&s_sq [c4 * 4 + 0], sq0);
        atomicAdd(&s_sq [c4 * 4 + 1], sq1);
        atomicAdd(&s_sq [c4 * 4 + 2], sq2);
        atomicAdd(&s_sq [c4 * 4 + 3], sq3);
    }
    __syncthreads();
    if (t < 64) {
        atomicAdd(&g_sum[layer][t], s_sum[t]);
        atomicAdd(&g_sq[layer][t], s_sq[t]);
    }
}

// BN apply with in-block prep: scale/shift from g_sum[1]/g_sq[1]
__global__ void bnapply_kernel(const float* __restrict__ v,
                               const float* __restrict__ gamma, const float* __restrict__ beta,
                               float* __restrict__ out) {
    __shared__ float sc[64], sf[64];
    int t = threadIdx.x;
    if (t < 64) {
        float m   = g_sum[1][t] * (1.0f / NN);
        float var = g_sq[1][t] * (1.0f / NN) - m * m;
        float s   = gamma[t] * rsqrtf(var + BN_EPS);
        sc[t] = s;
        sf[t] = beta[t] - m * s;
    }
    __syncthreads();
    int idx = blockIdx.x * blockDim.x + t;
    if (idx >= NN * 16) return;
    float4 x = reinterpret_cast<const float4*>(v)[idx];
    int c = (idx & 15) * 4;
    x.x = fmaxf(fmaf(x.x, sc[c + 0], sf[c + 0]), 0.f);
    x.y = fmaxf(fmaf(x.y, sc[c + 1], sf[c + 1]), 0.f);
    x.z = fmaxf(fmaf(x.z, sc[c + 2], sf[c + 2]), 0.f);
    x.w = fmaxf(fmaf(x.w, sc[c + 3], sf[c + 3]), 0.f);
    reinterpret_cast<float4*>(out)[idx] = x;
}

// ---------------- launch ----------------
extern "C" void kernel_launch(void* const* d_in, const int* in_sizes, int n_in,
                              void* d_out, int out_size) {
    const float* x   = (const float*)d_in[0];
    const int*   ei  = (const int*)d_in[1];
    const float* W1  = (const float*)d_in[2];
    const float* b1  = (const float*)d_in[3];
    const float* g1  = (const float*)d_in[4];
    const float* bt1 = (const float*)d_in[5];
    const float* W2  = (const float*)d_in[6];
    const float* b2  = (const float*)d_in[7];
    const float* g2  = (const float*)d_in[8];
    const float* bt2 = (const float*)d_in[9];
    float* out = (float*)d_out;

    const int* src = ei;
    const int* dst = ei + EE;

    __half2* hP = nullptr;
    float* aggP = nullptr;
    cudaGetSymbolAddress((void**)&hP, g_h);
    cudaGetSymbolAddress((void**)&aggP, g_agg);

    const int NB = (NN + 1023) / 1024;  // 98
    const int AGG_BLOCKS = 888;         // 148 SMs * 6 resident blocks (one full wave)
    const int SMEM1 = 512 + 128 * (INF + 8) * 2 + 64 * (INF + 8) * 2;  // 52736
    const int SMEM2 = 512 + 128 * (HH + 8) * 2 + 64 * (HH + 8) * 2;    // 28160

    cudaFuncSetAttribute(mma_gemm_kernel<INF, 0, 1>,
                         cudaFuncAttributeMaxDynamicSharedMemorySize, SMEM1);
    cudaFuncSetAttribute(mma_gemm_kernel<HH, 1, 0>,
                         cudaFuncAttributeMaxDynamicSharedMemorySize, SMEM2);

    hist_kernel<<<(EE + 255) / 256, 256>>>(dst);
    degscan_kernel<<<NB, 1024>>>(NB);

    // ---- layer 1 (CSR fill fused into GEMM1) ----
    mma_gemm_kernel<INF, 0, 1><<<(NN + 127) / 128, 256, SMEM1>>>(x, W1, hP, nullptr, nullptr, src, dst);
    aggstats_kernel<<<AGG_BLOCKS, 256>>>(hP, b1, aggP, 0);

    // ---- layer 2: BN(layer1)+ReLU fused into A-tile load ----
    mma_gemm_kernel<HH, 1, 0><<<(NN + 127) / 128, 256, SMEM2>>>(aggP, W2, hP, g1, bt1, nullptr, nullptr);
    aggstats_kernel<<<AGG_BLOCKS, 256>>>(hP, b2, aggP, 1);
    bnapply_kernel<<<(NN * 16 + 255) / 256, 256>>>(aggP, g2, bt2, out);
}

// round 12
// speedup vs baseline: 1.1244x; 1.0149x over previous
#include <cuda_runtime.h>
#include <cuda_bf16.h>
#include <cuda_fp16.h>
#include <math.h>
#include <stdint.h>

#define NN 100000
#define EE 1000000
#define INF 128
#define HH 64
#define BN_EPS 1e-5f

typedef unsigned long long ull;

// ---------------- scratch (device globals, no runtime alloc) ----------------
// Invariant: g_indeg is all-zero at every kernel_launch entry (zero-initialized at
// module load; degscan re-zeros it after use on every execution).
__device__ int   g_indeg[NN];
__device__ int   g_off[NN + 1];
__device__ int   g_rank[EE];
__device__ int   g_csr[EE];
__device__ float g_dinv[NN];
__device__ int   g_bsum[128];
__device__ int   g_boff[128];
__device__ int   g_ticket;
__device__ int   g_flag;
__device__ float g_sum[2][HH];
__device__ float g_sq[2][HH];

__device__ float g_h[(size_t)NN * HH];    // GEMM output (fp32), pre-scaled by dinv[row]
__device__ float g_agg[(size_t)NN * HH];  // aggregation output (pre-BN, fp32)

// packed dual-fp32 add (Blackwell; ptxas never emits this from C++)
__device__ __forceinline__ ull add2(ull a, ull b) {
    ull d;
    asm("add.rn.f32x2 %0, %1, %2;" : "=l"(d) : "l"(a), "l"(b));
    return d;
}

// ---------------- graph build ----------------

// histogram + per-edge rank; also resets per-call scalars/stats (indeg is pre-zeroed)
__global__ void hist_kernel(const int* __restrict__ dst) {
    int e = blockIdx.x * blockDim.x + threadIdx.x;
    if (e < EE) g_rank[e] = atomicAdd(&g_indeg[dst[e]], 1);
    if (e == 0) { g_ticket = 0; g_flag = 0; }
    if (e < 2 * HH) {
        ((float*)g_sum)[e] = 0.f;
        ((float*)g_sq)[e]  = 0.f;
    }
}

// fused: per-block inclusive scan + cross-block scan (last-block election) + finalize
// + self-clean (re-zero indeg). 98 blocks, all resident -> flag spin is safe.
__global__ void degscan_kernel(int nb) {
    __shared__ int sh[1024];
    __shared__ int amLast;
    int t = threadIdx.x;
    int b = blockIdx.x;
    int idx = b * 1024 + t;
    int v = (idx < NN) ? g_indeg[idx] : 0;
    sh[t] = v;
    __syncthreads();
    for (int o = 1; o < 1024; o <<= 1) {
        int a = (t >= o) ? sh[t - o] : 0;
        __syncthreads();
        sh[t] += a;
        __syncthreads();
    }
    int incl = sh[t];
    if (t == 1023) {
        g_bsum[b] = incl;
        __threadfence();
        amLast = (atomicAdd(&g_ticket, 1) == gridDim.x - 1);
    }
    __syncthreads();
    if (amLast) {
        int bv = (t < nb) ? g_bsum[t] : 0;
        sh[t] = (t < 128) ? bv : 0;
        __syncthreads();
        for (int o = 1; o < 128; o <<= 1) {
            int a = (t >= o && t < 128) ? sh[t - o] : 0;
            __syncthreads();
            if (t < 128) sh[t] += a;
            __syncthreads();
        }
        if (t < nb) g_boff[t] = sh[t] - bv;
        if (t == nb - 1) g_off[NN] = sh[t];
        __threadfence();
        if (t == 0) atomicExch(&g_flag, 1);
    }
    if (t == 0) {
        while (atomicAdd(&g_flag, 0) == 0) {}
    }
    __syncthreads();
    if (idx < NN) {
        int off = g_boff[b] + incl - v;
        g_off[idx] = off;
        g_dinv[idx] = rsqrtf((float)(v + 1));   // deg = indeg + self-loop
        g_indeg[idx] = 0;                        // self-clean for next call
    }
}

// ---------------- HMMA GEMM (mma.sync m16n8k16, fp16 in / fp32 accum) ----------------

__device__ __forceinline__ uint32_t smem_u32(const void* p) {
    uint32_t a;
    asm("{ .reg .u64 t; cvta.to.shared.u64 t, %1; cvt.u32.u64 %0, t; }" : "=r"(a) : "l"(p));
    return a;
}

__device__ __forceinline__ void ldmat_x4(uint32_t& r0, uint32_t& r1, uint32_t& r2, uint32_t& r3,
                                         uint32_t addr) {
    asm volatile("ldmatrix.sync.aligned.m8n8.x4.shared.b16 {%0,%1,%2,%3}, [%4];"
                 : "=r"(r0), "=r"(r1), "=r"(r2), "=r"(r3) : "r"(addr));
}

__device__ __forceinline__ void mma_16816(float& c0, float& c1, float& c2, float& c3,
                                          uint32_t a0, uint32_t a1, uint32_t a2, uint32_t a3,
                                          uint32_t b0, uint32_t b1) {
    asm volatile("mma.sync.aligned.m16n8k16.row.col.f32.f16.f16.f32 "
                 "{%0,%1,%2,%3}, {%4,%5,%6,%7}, {%8,%9}, {%0,%1,%2,%3};"
                 : "+f"(c0), "+f"(c1), "+f"(c2), "+f"(c3)
                 : "r"(a0), "r"(a1), "r"(a2), "r"(a3), "r"(b0), "r"(b1));
}

template <int K, int DO_BN, int DO_FILL>
__global__ __launch_bounds__(256, 2)
void mma_gemm_kernel(const float* __restrict__ A, const float* __restrict__ W,
                     float* __restrict__ C,
                     const float* __restrict__ gamma, const float* __restrict__ beta,
                     const int* __restrict__ src, const int* __restrict__ dst) {
    extern __shared__ char smem[];
    const int KS = K + 8;
    const int A_OFF = 512;
    const int B_OFF = A_OFF + 128 * KS * 2;
    float* s_scale = (float*)(smem + 0);
    float* s_shift = (float*)(smem + 256);
    __half* As = (__half*)(smem + A_OFF);
    __half* Bs = (__half*)(smem + B_OFF);

    int t = threadIdx.x;
    int wid = t >> 5;
    int lane = t & 31;
    int m0 = blockIdx.x * 128;

    if (DO_BN) {
        if (t < 64) {
            float m   = g_sum[0][t] * (1.0f / NN);
            float var = g_sq[0][t] * (1.0f / NN) - m * m;
            float sc  = gamma[t] * rsqrtf(var + BN_EPS);
            s_scale[t] = sc;
            s_shift[t] = beta[t] - m * sc;
        }
        __syncthreads();
    }

    // ---- A tile: fp32 -> (BN+ReLU) -> fp16 ----
    const int QK = K / 4;
    for (int idx = t; idx < 128 * QK; idx += 256) {
        int r = idx / QK;
        int q = idx - r * QK;
        int k = q * 4;
        int row = m0 + r;
        float4 v = make_float4(0.f, 0.f, 0.f, 0.f);
        if (row < NN) v = *reinterpret_cast<const float4*>(A + (size_t)row * K + k);
        if (DO_BN) {
            v.x = fmaxf(fmaf(v.x, s_scale[k + 0], s_shift[k + 0]), 0.f);
            v.y = fmaxf(fmaf(v.y, s_scale[k + 1], s_shift[k + 1]), 0.f);
            v.z = fmaxf(fmaf(v.z, s_scale[k + 2], s_shift[k + 2]), 0.f);
            v.w = fmaxf(fmaf(v.w, s_scale[k + 3], s_shift[k + 3]), 0.f);
        }
        __half2 h01 = __floats2half2_rn(v.x, v.y);
        __half2 h23 = __floats2half2_rn(v.z, v.w);
        ull pk = (ull)(*reinterpret_cast<uint32_t*>(&h01)) |
                 ((ull)(*reinterpret_cast<uint32_t*>(&h23)) << 32);
        *reinterpret_cast<ull*>(&As[r * KS + k]) = pk;
    }

    // ---- B tile = W^T: Bs[n][k] = W[k][n] ----
    for (int idx = t; idx < K * 64; idx += 256) {
        int k = idx >> 6;
        int n = idx & 63;
        Bs[n * KS + k] = __float2half_rn(W[idx]);
    }
    __syncthreads();

    float acc[8][4];
#pragma unroll
    for (int nb = 0; nb < 8; nb++)
#pragma unroll
        for (int j = 0; j < 4; j++) acc[nb][j] = 0.f;

    uint32_t as_base = smem_u32(As);
    uint32_t bs_base = smem_u32(Bs);

    uint32_t a_row = wid * 16 + (lane & 15);
    uint32_t a_addr0 = as_base + (a_row * KS + (lane >> 4) * 8) * 2;
    uint32_t b_n = (lane & 7) + ((lane >> 4) & 1) * 8;
    uint32_t b_k = ((lane >> 3) & 1) * 8;
    uint32_t b_addr0 = bs_base + (b_n * KS + b_k) * 2;

#pragma unroll
    for (int ks = 0; ks < K / 16; ks++) {
        uint32_t a0, a1, a2, a3;
        ldmat_x4(a0, a1, a2, a3, a_addr0 + ks * 32);
#pragma unroll
        for (int nb2 = 0; nb2 < 4; nb2++) {
            uint32_t b0, b1, b2, b3;
            ldmat_x4(b0, b1, b2, b3, b_addr0 + (nb2 * 16 * KS + ks * 16) * 2);
            mma_16816(acc[nb2 * 2 + 0][0], acc[nb2 * 2 + 0][1], acc[nb2 * 2 + 0][2], acc[nb2 * 2 + 0][3],
                      a0, a1, a2, a3, b0, b1);
            mma_16816(acc[nb2 * 2 + 1][0], acc[nb2 * 2 + 1][1], acc[nb2 * 2 + 1][2], acc[nb2 * 2 + 1][3],
                      a0, a1, a2, a3, b2, b3);
        }
    }

    int g = lane >> 2;
    int tq = lane & 3;
    int row0 = m0 + wid * 16 + g;
    int row1 = row0 + 8;
    if (row0 < NN) {
        float di = g_dinv[row0];
#pragma unroll
        for (int nb = 0; nb < 8; nb++) {
            float2 o = make_float2(acc[nb][0] * di, acc[nb][1] * di);
            *reinterpret_cast<float2*>(C + (size_t)row0 * 64 + nb * 8 + tq * 2) = o;
        }
    }
    if (row1 < NN) {
        float di = g_dinv[row1];
#pragma unroll
        for (int nb = 0; nb < 8; nb++) {
            float2 o = make_float2(acc[nb][2] * di, acc[nb][3] * di);
            *reinterpret_cast<float2*>(C + (size_t)row1 * 64 + nb * 8 + tq * 2) = o;
        }
    }

    // ---- fused CSR fill (independent; overlaps other blocks' MMA) ----
    if (DO_FILL) {
        int stride = gridDim.x * 256;
        for (int e = blockIdx.x * 256 + t; e < EE; e += stride)
            g_csr[g_off[dst[e]] + g_rank[e]] = src[e];
    }
}

// ---------------- aggregation (fp32 float4 gather, packed f32x2 accum) + BN stats ----------------
// 2 edges per warp memory-iteration: lanes 0-15 gather even edges, 16-31 odd edges,
// each lane loading float4 (4 channels, 16B) so 16 lanes cover a full 256B row.
// Zero cvt instructions; adds done 2-at-a-time via add.rn.f32x2.
__global__ __launch_bounds__(256, 6)
void aggstats_kernel(const float* __restrict__ h, const float* __restrict__ bias,
                     float* __restrict__ out, int layer) {
    __shared__ float s_sum[64], s_sq[64];
    int t = threadIdx.x;
    if (t < 64) { s_sum[t] = 0.f; s_sq[t] = 0.f; }
    __syncthreads();
    int lane = t & 31;
    int c4 = lane & 15;          // float4 slot: channels 4*c4 .. 4*c4+3
    int hw = lane >> 4;          // 0: even edges, 1: odd edges
    int warpId = blockIdx.x * (blockDim.x >> 5) + (t >> 5);
    int totalWarps = gridDim.x * (blockDim.x >> 5);
    const float4* h4 = reinterpret_cast<const float4*>(h);  // 16 float4 per row
    float4 b4 = reinterpret_cast<const float4*>(bias)[c4];
    float sm0 = 0.f, sm1 = 0.f, sm2 = 0.f, sm3 = 0.f;
    float sq0 = 0.f, sq1 = 0.f, sq2 = 0.f, sq3 = 0.f;

    for (int i = warpId; i < NN; i += totalWarps) {
        float di = g_dinv[i];
        ulonglong2 a2;              // packed acc: (ch0,ch1),(ch2,ch3)
        if (hw == 0) {              // self-loop (pre-scaled) seeds the even half
            float4 sv = h4[(unsigned)i * 16u + c4];
            a2 = *reinterpret_cast<ulonglong2*>(&sv);
        } else {
            a2.x = 0ull; a2.y = 0ull;
        }
        int e0 = g_off[i], e1 = g_off[i + 1];
        int j = e0 + hw;
        for (; j + 6 < e1; j += 8) {
            int s0 = g_csr[j], s1 = g_csr[j + 2], s2 = g_csr[j + 4], s3 = g_csr[j + 6];
            float4 v0 = h4[(unsigned)s0 * 16u + c4];
            float4 v1 = h4[(unsigned)s1 * 16u + c4];
            float4 v2 = h4[(unsigned)s2 * 16u + c4];
            float4 v3 = h4[(unsigned)s3 * 16u + c4];
            ulonglong2 u0 = *reinterpret_cast<ulonglong2*>(&v0);
            ulonglong2 u1 = *reinterpret_cast<ulonglong2*>(&v1);
            ulonglong2 u2 = *reinterpret_cast<ulonglong2*>(&v2);
            ulonglong2 u3 = *reinterpret_cast<ulonglong2*>(&v3);
            u0.x = add2(u0.x, u1.x); u0.y = add2(u0.y, u1.y);
            u2.x = add2(u2.x, u3.x); u2.y = add2(u2.y, u3.y);
            u0.x = add2(u0.x, u2.x); u0.y = add2(u0.y, u2.y);
            a2.x = add2(a2.x, u0.x); a2.y = add2(a2.y, u0.y);
        }
        for (; j < e1; j += 2) {
            float4 v = h4[(unsigned)g_csr[j] * 16u + c4];
            ulonglong2 u = *reinterpret_cast<ulonglong2*>(&v);
            a2.x = add2(a2.x, u.x);
            a2.y = add2(a2.y, u.y);
        }
        float4 acc = *reinterpret_cast<float4*>(&a2);
        // combine odd half into even half
        acc.x += __shfl_down_sync(0xffffffffu, acc.x, 16);
        acc.y += __shfl_down_sync(0xffffffffu, acc.y, 16);
        acc.z += __shfl_down_sync(0xffffffffu, acc.z, 16);
        acc.w += __shfl_down_sync(0xffffffffu, acc.w, 16);
        if (hw == 0) {
            float4 o;
            o.x = fmaf(acc.x, di, b4.x);
            o.y = fmaf(acc.y, di, b4.y);
            o.z = fmaf(acc.z, di, b4.z);
            o.w = fmaf(acc.w, di, b4.w);
            reinterpret_cast<float4*>(out)[(unsigned)i * 16u + c4] = o;
            sm0 += o.x; sq0 += o.x * o.x;
            sm1 += o.y; sq1 += o.y * o.y;
            sm2 += o.z; sq2 += o.z * o.z;
            sm3 += o.w; sq3 += o.w * o.w;
        }
    }
    if (hw == 0) {
        atomicAdd(&s_sum[c4 * 4 + 0], sm0);
        atomicAdd(&s_sum[c4 * 4 + 1], sm1);
        atomicAdd(&s_sum[c4 * 4 + 2], sm2);
        atomicAdd(&s_sum[c4 * 4 + 3], sm3);
        atomicAdd(&s_sq [c4 * 4 + 0], sq0);
        atomicAdd(&s_sq [c4 * 4 + 1], sq1);
        atomicAdd(&s_sq [c4 * 4 + 2], sq2);
        atomicAdd(&s_sq [c4 * 4 + 3], sq3);
    }
    __syncthreads();
    if (t < 64) {
        atomicAdd(&g_sum[layer][t], s_sum[t]);
        atomicAdd(&g_sq[layer][t], s_sq[t]);
    }
}

// BN apply with in-block prep: scale/shift from g_sum[1]/g_sq[1]
__global__ void bnapply_kernel(const float* __restrict__ v,
                               const float* __restrict__ gamma, const float* __restrict__ beta,
                               float* __restrict__ out) {
    __shared__ float sc[64], sf[64];
    int t = threadIdx.x;
    if (t < 64) {
        float m   = g_sum[1][t] * (1.0f / NN);
        float var = g_sq[1][t] * (1.0f / NN) - m * m;
        float s   = gamma[t] * rsqrtf(var + BN_EPS);
        sc[t] = s;
        sf[t] = beta[t] - m * s;
    }
    __syncthreads();
    int idx = blockIdx.x * blockDim.x + t;
    if (idx >= NN * 16) return;
    float4 x = reinterpret_cast<const float4*>(v)[idx];
    int c = (idx & 15) * 4;
    x.x = fmaxf(fmaf(x.x, sc[c + 0], sf[c + 0]), 0.f);
    x.y = fmaxf(fmaf(x.y, sc[c + 1], sf[c + 1]), 0.f);
    x.z = fmaxf(fmaf(x.z, sc[c + 2], sf[c + 2]), 0.f);
    x.w = fmaxf(fmaf(x.w, sc[c + 3], sf[c + 3]), 0.f);
    reinterpret_cast<float4*>(out)[idx] = x;
}

// ---------------- launch ----------------
extern "C" void kernel_launch(void* const* d_in, const int* in_sizes, int n_in,
                              void* d_out, int out_size) {
    const float* x   = (const float*)d_in[0];
    const int*   ei  = (const int*)d_in[1];
    const float* W1  = (const float*)d_in[2];
    const float* b1  = (const float*)d_in[3];
    const float* g1  = (const float*)d_in[4];
    const float* bt1 = (const float*)d_in[5];
    const float* W2  = (const float*)d_in[6];
    const float* b2  = (const float*)d_in[7];
    const float* g2  = (const float*)d_in[8];
    const float* bt2 = (const float*)d_in[9];
    float* out = (float*)d_out;

    const int* src = ei;
    const int* dst = ei + EE;

    float *hP = nullptr, *aggP = nullptr;
    cudaGetSymbolAddress((void**)&hP, g_h);
    cudaGetSymbolAddress((void**)&aggP, g_agg);

    const int NB = (NN + 1023) / 1024;  // 98
    const int AGG_BLOCKS = 888;         // 148 SMs * 6 resident blocks
    const int SMEM1 = 512 + 128 * (INF + 8) * 2 + 64 * (INF + 8) * 2;  // 52736
    const int SMEM2 = 512 + 128 * (HH + 8) * 2 + 64 * (HH + 8) * 2;    // 28160

    cudaFuncSetAttribute(mma_gemm_kernel<INF, 0, 1>,
                         cudaFuncAttributeMaxDynamicSharedMemorySize, SMEM1);
    cudaFuncSetAttribute(mma_gemm_kernel<HH, 1, 0>,
                         cudaFuncAttributeMaxDynamicSharedMemorySize, SMEM2);

    hist_kernel<<<(EE + 255) / 256, 256>>>(dst);
    degscan_kernel<<<NB, 1024>>>(NB);

    // ---- layer 1 (CSR fill fused into GEMM1) ----
    mma_gemm_kernel<INF, 0, 1><<<(NN + 127) / 128, 256, SMEM1>>>(x, W1, hP, nullptr, nullptr, src, dst);
    aggstats_kernel<<<AGG_BLOCKS, 256>>>(hP, b1, aggP, 0);

    // ---- layer 2: BN(layer1)+ReLU fused into A-tile load ----
    mma_gemm_kernel<HH, 1, 0><<<(NN + 127) / 128, 256, SMEM2>>>(aggP, W2, hP, g1, bt1, nullptr, nullptr);
    aggstats_kernel<<<AGG_BLOCKS, 256>>>(hP, b2, aggP, 1);
    bnapply_kernel<<<(NN * 16 + 255) / 256, 256>>>(aggP, g2, bt2, out);
}

// round 13
// speedup vs baseline: 1.1569x; 1.0289x over previous
#include <cuda_runtime.h>
#include <cuda_bf16.h>
#include <cuda_fp16.h>
#include <math.h>
#include <stdint.h>

#define NN 100000
#define EE 1000000
#define INF 128
#define HH 64
#define BN_EPS 1e-5f

typedef unsigned long long ull;

// ---------------- scratch (device globals, no runtime alloc) ----------------
// Invariant: g_indeg is all-zero at every kernel_launch entry (zero-initialized at
// module load; degscan re-zeros it after use on every execution).
__device__ int   g_indeg[NN];
__device__ uint2 g_offcnt[NN];     // {csr offset, indegree}
__device__ int   g_rank[EE];
__device__ int   g_csr[EE];
__device__ float g_dinv[NN];
__device__ int   g_bsum[128];
__device__ int   g_boff[128];
__device__ int   g_ticket;
__device__ int   g_flag;
__device__ float g_sum[2][HH];
__device__ float g_sq[2][HH];

__device__ float g_h[(size_t)NN * HH];    // GEMM output (fp32), pre-scaled by dinv[row]
__device__ float g_agg[(size_t)NN * HH];  // aggregation output (pre-BN, fp32)

// packed dual-fp32 add (Blackwell; ptxas never emits this from C++)
__device__ __forceinline__ ull add2(ull a, ull b) {
    ull d;
    asm("add.rn.f32x2 %0, %1, %2;" : "=l"(d) : "l"(a), "l"(b));
    return d;
}

// ---------------- graph build ----------------

// histogram + per-edge rank; also resets per-call scalars/stats (indeg is pre-zeroed)
__global__ void hist_kernel(const int* __restrict__ dst) {
    int e = blockIdx.x * blockDim.x + threadIdx.x;
    if (e < EE) g_rank[e] = atomicAdd(&g_indeg[dst[e]], 1);
    if (e == 0) { g_ticket = 0; g_flag = 0; }
    if (e < 2 * HH) {
        ((float*)g_sum)[e] = 0.f;
        ((float*)g_sq)[e]  = 0.f;
    }
}

// fused: per-block inclusive scan + cross-block scan (last-block election) + finalize
// + self-clean (re-zero indeg). 98 blocks, all resident -> flag spin is safe.
__global__ void degscan_kernel(int nb) {
    __shared__ int sh[1024];
    __shared__ int amLast;
    int t = threadIdx.x;
    int b = blockIdx.x;
    int idx = b * 1024 + t;
    int v = (idx < NN) ? g_indeg[idx] : 0;
    sh[t] = v;
    __syncthreads();
    for (int o = 1; o < 1024; o <<= 1) {
        int a = (t >= o) ? sh[t - o] : 0;
        __syncthreads();
        sh[t] += a;
        __syncthreads();
    }
    int incl = sh[t];
    if (t == 1023) {
        g_bsum[b] = incl;
        __threadfence();
        amLast = (atomicAdd(&g_ticket, 1) == gridDim.x - 1);
    }
    __syncthreads();
    if (amLast) {
        int bv = (t < nb) ? g_bsum[t] : 0;
        sh[t] = (t < 128) ? bv : 0;
        __syncthreads();
        for (int o = 1; o < 128; o <<= 1) {
            int a = (t >= o && t < 128) ? sh[t - o] : 0;
            __syncthreads();
            if (t < 128) sh[t] += a;
            __syncthreads();
        }
        if (t < nb) g_boff[t] = sh[t] - bv;
        __threadfence();
        if (t == 0) atomicExch(&g_flag, 1);
    }
    if (t == 0) {
        while (atomicAdd(&g_flag, 0) == 0) {}
    }
    __syncthreads();
    if (idx < NN) {
        int off = g_boff[b] + incl - v;
        g_offcnt[idx] = make_uint2((unsigned)off, (unsigned)v);
        g_dinv[idx] = rsqrtf((float)(v + 1));   // deg = indeg + self-loop (GEMM epilogue)
        g_indeg[idx] = 0;                        // self-clean for next call
    }
}

// ---------------- HMMA GEMM (mma.sync m16n8k16, fp16 in / fp32 accum) ----------------

__device__ __forceinline__ uint32_t smem_u32(const void* p) {
    uint32_t a;
    asm("{ .reg .u64 t; cvta.to.shared.u64 t, %1; cvt.u32.u64 %0, t; }" : "=r"(a) : "l"(p));
    return a;
}

__device__ __forceinline__ void ldmat_x4(uint32_t& r0, uint32_t& r1, uint32_t& r2, uint32_t& r3,
                                         uint32_t addr) {
    asm volatile("ldmatrix.sync.aligned.m8n8.x4.shared.b16 {%0,%1,%2,%3}, [%4];"
                 : "=r"(r0), "=r"(r1), "=r"(r2), "=r"(r3) : "r"(addr));
}

__device__ __forceinline__ void mma_16816(float& c0, float& c1, float& c2, float& c3,
                                          uint32_t a0, uint32_t a1, uint32_t a2, uint32_t a3,
                                          uint32_t b0, uint32_t b1) {
    asm volatile("mma.sync.aligned.m16n8k16.row.col.f32.f16.f16.f32 "
                 "{%0,%1,%2,%3}, {%4,%5,%6,%7}, {%8,%9}, {%0,%1,%2,%3};"
                 : "+f"(c0), "+f"(c1), "+f"(c2), "+f"(c3)
                 : "r"(a0), "r"(a1), "r"(a2), "r"(a3), "r"(b0), "r"(b1));
}

template <int K, int DO_BN, int DO_FILL>
__global__ __launch_bounds__(256, 2)
void mma_gemm_kernel(const float* __restrict__ A, const float* __restrict__ W,
                     float* __restrict__ C,
                     const float* __restrict__ gamma, const float* __restrict__ beta,
                     const int* __restrict__ src, const int* __restrict__ dst) {
    extern __shared__ char smem[];
    const int KS = K + 8;
    const int A_OFF = 512;
    const int B_OFF = A_OFF + 128 * KS * 2;
    float* s_scale = (float*)(smem + 0);
    float* s_shift = (float*)(smem + 256);
    __half* As = (__half*)(smem + A_OFF);
    __half* Bs = (__half*)(smem + B_OFF);

    int t = threadIdx.x;
    int wid = t >> 5;
    int lane = t & 31;
    int m0 = blockIdx.x * 128;

    if (DO_BN) {
        if (t < 64) {
            float m   = g_sum[0][t] * (1.0f / NN);
            float var = g_sq[0][t] * (1.0f / NN) - m * m;
            float sc  = gamma[t] * rsqrtf(var + BN_EPS);
            s_scale[t] = sc;
            s_shift[t] = beta[t] - m * sc;
        }
        __syncthreads();
    }

    // ---- A tile: fp32 -> (BN+ReLU) -> fp16 ----
    const int QK = K / 4;
    for (int idx = t; idx < 128 * QK; idx += 256) {
        int r = idx / QK;
        int q = idx - r * QK;
        int k = q * 4;
        int row = m0 + r;
        float4 v = make_float4(0.f, 0.f, 0.f, 0.f);
        if (row < NN) v = *reinterpret_cast<const float4*>(A + (size_t)row * K + k);
        if (DO_BN) {
            v.x = fmaxf(fmaf(v.x, s_scale[k + 0], s_shift[k + 0]), 0.f);
            v.y = fmaxf(fmaf(v.y, s_scale[k + 1], s_shift[k + 1]), 0.f);
            v.z = fmaxf(fmaf(v.z, s_scale[k + 2], s_shift[k + 2]), 0.f);
            v.w = fmaxf(fmaf(v.w, s_scale[k + 3], s_shift[k + 3]), 0.f);
        }
        __half2 h01 = __floats2half2_rn(v.x, v.y);
        __half2 h23 = __floats2half2_rn(v.z, v.w);
        ull pk = (ull)(*reinterpret_cast<uint32_t*>(&h01)) |
                 ((ull)(*reinterpret_cast<uint32_t*>(&h23)) << 32);
        *reinterpret_cast<ull*>(&As[r * KS + k]) = pk;
    }

    // ---- B tile = W^T: Bs[n][k] = W[k][n] ----
    for (int idx = t; idx < K * 64; idx += 256) {
        int k = idx >> 6;
        int n = idx & 63;
        Bs[n * KS + k] = __float2half_rn(W[idx]);
    }
    __syncthreads();

    float acc[8][4];
#pragma unroll
    for (int nb = 0; nb < 8; nb++)
#pragma unroll
        for (int j = 0; j < 4; j++) acc[nb][j] = 0.f;

    uint32_t as_base = smem_u32(As);
    uint32_t bs_base = smem_u32(Bs);

    uint32_t a_row = wid * 16 + (lane & 15);
    uint32_t a_addr0 = as_base + (a_row * KS + (lane >> 4) * 8) * 2;
    uint32_t b_n = (lane & 7) + ((lane >> 4) & 1) * 8;
    uint32_t b_k = ((lane >> 3) & 1) * 8;
    uint32_t b_addr0 = bs_base + (b_n * KS + b_k) * 2;

#pragma unroll
    for (int ks = 0; ks < K / 16; ks++) {
        uint32_t a0, a1, a2, a3;
        ldmat_x4(a0, a1, a2, a3, a_addr0 + ks * 32);
#pragma unroll
        for (int nb2 = 0; nb2 < 4; nb2++) {
            uint32_t b0, b1, b2, b3;
            ldmat_x4(b0, b1, b2, b3, b_addr0 + (nb2 * 16 * KS + ks * 16) * 2);
            mma_16816(acc[nb2 * 2 + 0][0], acc[nb2 * 2 + 0][1], acc[nb2 * 2 + 0][2], acc[nb2 * 2 + 0][3],
                      a0, a1, a2, a3, b0, b1);
            mma_16816(acc[nb2 * 2 + 1][0], acc[nb2 * 2 + 1][1], acc[nb2 * 2 + 1][2], acc[nb2 * 2 + 1][3],
                      a0, a1, a2, a3, b2, b3);
        }
    }

    int g = lane >> 2;
    int tq = lane & 3;
    int row0 = m0 + wid * 16 + g;
    int row1 = row0 + 8;
    if (row0 < NN) {
        float di = g_dinv[row0];
#pragma unroll
        for (int nb = 0; nb < 8; nb++) {
            float2 o = make_float2(acc[nb][0] * di, acc[nb][1] * di);
            *reinterpret_cast<float2*>(C + (size_t)row0 * 64 + nb * 8 + tq * 2) = o;
        }
    }
    if (row1 < NN) {
        float di = g_dinv[row1];
#pragma unroll
        for (int nb = 0; nb < 8; nb++) {
            float2 o = make_float2(acc[nb][2] * di, acc[nb][3] * di);
            *reinterpret_cast<float2*>(C + (size_t)row1 * 64 + nb * 8 + tq * 2) = o;
        }
    }

    // ---- fused CSR fill (independent; overlaps other blocks' MMA) ----
    if (DO_FILL) {
        int stride = gridDim.x * 256;
        for (int e = blockIdx.x * 256 + t; e < EE; e += stride)
            g_csr[g_offcnt[dst[e]].x + g_rank[e]] = src[e];
    }
}

// ---------------- aggregation: half-warp per node, packed f32x2 accum + BN stats ----------------
// Each half-warp owns an independent node stream (two latency chains per warp).
// 16 lanes x float4 cover a 256B row; per node: one LDG.64 (off,cnt), dinv via rsqrt.
__global__ __launch_bounds__(256, 6)
void aggstats_kernel(const float* __restrict__ h, const float* __restrict__ bias,
                     float* __restrict__ out, int layer) {
    __shared__ float s_sum[64], s_sq[64];
    int t = threadIdx.x;
    if (t < 64) { s_sum[t] = 0.f; s_sq[t] = 0.f; }
    __syncthreads();
    int c4 = t & 15;             // float4 slot: channels 4*c4 .. 4*c4+3
    int hwId = (blockIdx.x * blockDim.x + t) >> 4;   // global half-warp id
    int totalHW = (gridDim.x * blockDim.x) >> 4;
    const float4* h4 = reinterpret_cast<const float4*>(h);  // 16 float4 per row
    float4 b4 = reinterpret_cast<const float4*>(bias)[c4];
    float sm0 = 0.f, sm1 = 0.f, sm2 = 0.f, sm3 = 0.f;
    float sq0 = 0.f, sq1 = 0.f, sq2 = 0.f, sq3 = 0.f;

    for (int i = hwId; i < NN; i += totalHW) {
        uint2 oc = g_offcnt[i];
        int e0 = (int)oc.x;
        int e1 = e0 + (int)oc.y;
        float di = rsqrtf((float)(oc.y + 1u));
        float4 sv = h4[(unsigned)i * 16u + c4];      // self-loop (pre-scaled)
        ulonglong2 a2 = *reinterpret_cast<ulonglong2*>(&sv);
        int j = e0;
        for (; j + 3 < e1; j += 4) {
            int s0 = g_csr[j], s1 = g_csr[j + 1], s2 = g_csr[j + 2], s3 = g_csr[j + 3];
            float4 v0 = h4[(unsigned)s0 * 16u + c4];
            float4 v1 = h4[(unsigned)s1 * 16u + c4];
            float4 v2 = h4[(unsigned)s2 * 16u + c4];
            float4 v3 = h4[(unsigned)s3 * 16u + c4];
            ulonglong2 u0 = *reinterpret_cast<ulonglong2*>(&v0);
            ulonglong2 u1 = *reinterpret_cast<ulonglong2*>(&v1);
            ulonglong2 u2 = *reinterpret_cast<ulonglong2*>(&v2);
            ulonglong2 u3 = *reinterpret_cast<ulonglong2*>(&v3);
            u0.x = add2(u0.x, u1.x); u0.y = add2(u0.y, u1.y);
            u2.x = add2(u2.x, u3.x); u2.y = add2(u2.y, u3.y);
            u0.x = add2(u0.x, u2.x); u0.y = add2(u0.y, u2.y);
            a2.x = add2(a2.x, u0.x); a2.y = add2(a2.y, u0.y);
        }
        for (; j < e1; j++) {
            float4 v = h4[(unsigned)g_csr[j] * 16u + c4];
            ulonglong2 u = *reinterpret_cast<ulonglong2*>(&v);
            a2.x = add2(a2.x, u.x);
            a2.y = add2(a2.y, u.y);
        }
        float4 acc = *reinterpret_cast<float4*>(&a2);
        float4 o;
        o.x = fmaf(acc.x, di, b4.x);
        o.y = fmaf(acc.y, di, b4.y);
        o.z = fmaf(acc.z, di, b4.z);
        o.w = fmaf(acc.w, di, b4.w);
        reinterpret_cast<float4*>(out)[(unsigned)i * 16u + c4] = o;
        sm0 += o.x; sq0 += o.x * o.x;
        sm1 += o.y; sq1 += o.y * o.y;
        sm2 += o.z; sq2 += o.z * o.z;
        sm3 += o.w; sq3 += o.w * o.w;
    }
    atomicAdd(&s_sum[c4 * 4 + 0], sm0);
    atomicAdd(&s_sum[c4 * 4 + 1], sm1);
    atomicAdd(&s_sum[c4 * 4 + 2], sm2);
    atomicAdd(&s_sum[c4 * 4 + 3], sm3);
    atomicAdd(&s_sq [c4 * 4 + 0], sq0);
    atomicAdd(&s_sq [c4 * 4 + 1], sq1);
    atomicAdd(&s_sq [c4 * 4 + 2], sq2);
    atomicAdd(&s_sq [c4 * 4 + 3], sq3);
    __syncthreads();
    if (t < 64) {
        atomicAdd(&g_sum[layer][t], s_sum[t]);
        atomicAdd(&g_sq[layer][t], s_sq[t]);
    }
}

// BN apply with in-block prep: scale/shift from g_sum[1]/g_sq[1]
__global__ void bnapply_kernel(const float* __restrict__ v,
                               const float* __restrict__ gamma, const float* __restrict__ beta,
                               float* __restrict__ out) {
    __shared__ float sc[64], sf[64];
    int t = threadIdx.x;
    if (t < 64) {
        float m   = g_sum[1][t] * (1.0f / NN);
        float var = g_sq[1][t] * (1.0f / NN) - m * m;
        float s   = gamma[t] * rsqrtf(var + BN_EPS);
        sc[t] = s;
        sf[t] = beta[t] - m * s;
    }
    __syncthreads();
    int idx = blockIdx.x * blockDim.x + t;
    if (idx >= NN * 16) return;
    float4 x = reinterpret_cast<const float4*>(v)[idx];
    int c = (idx & 15) * 4;
    x.x = fmaxf(fmaf(x.x, sc[c + 0], sf[c + 0]), 0.f);
    x.y = fmaxf(fmaf(x.y, sc[c + 1], sf[c + 1]), 0.f);
    x.z = fmaxf(fmaf(x.z, sc[c + 2], sf[c + 2]), 0.f);
    x.w = fmaxf(fmaf(x.w, sc[c + 3], sf[c + 3]), 0.f);
    reinterpret_cast<float4*>(out)[idx] = x;
}

// ---------------- launch ----------------
extern "C" void kernel_launch(void* const* d_in, const int* in_sizes, int n_in,
                              void* d_out, int out_size) {
    const float* x   = (const float*)d_in[0];
    const int*   ei  = (const int*)d_in[1];
    const float* W1  = (const float*)d_in[2];
    const float* b1  = (const float*)d_in[3];
    const float* g1  = (const float*)d_in[4];
    const float* bt1 = (const float*)d_in[5];
    const float* W2  = (const float*)d_in[6];
    const float* b2  = (const float*)d_in[7];
    const float* g2  = (const float*)d_in[8];
    const float* bt2 = (const float*)d_in[9];
    float* out = (float*)d_out;

    const int* src = ei;
    const int* dst = ei + EE;

    float *hP = nullptr, *aggP = nullptr;
    cudaGetSymbolAddress((void**)&hP, g_h);
    cudaGetSymbolAddress((void**)&aggP, g_agg);

    const int NB = (NN + 1023) / 1024;  // 98
    const int AGG_BLOCKS = 888;         // 148 SMs * 6 resident blocks
    const int SMEM1 = 512 + 128 * (INF + 8) * 2 + 64 * (INF + 8) * 2;  // 52736
    const int SMEM2 = 512 + 128 * (HH + 8) * 2 + 64 * (HH + 8) * 2;    // 28160

    cudaFuncSetAttribute(mma_gemm_kernel<INF, 0, 1>,
                         cudaFuncAttributeMaxDynamicSharedMemorySize, SMEM1);
    cudaFuncSetAttribute(mma_gemm_kernel<HH, 1, 0>,
                         cudaFuncAttributeMaxDynamicSharedMemorySize, SMEM2);

    hist_kernel<<<(EE + 255) / 256, 256>>>(dst);
    degscan_kernel<<<NB, 1024>>>(NB);

    // ---- layer 1 (CSR fill fused into GEMM1) ----
    mma_gemm_kernel<INF, 0, 1><<<(NN + 127) / 128, 256, SMEM1>>>(x, W1, hP, nullptr, nullptr, src, dst);
    aggstats_kernel<<<AGG_BLOCKS, 256>>>(hP, b1, aggP, 0);

    // ---- layer 2: BN(layer1)+ReLU fused into A-tile load ----
    mma_gemm_kernel<HH, 1, 0><<<(NN + 127) / 128, 256, SMEM2>>>(aggP, W2, hP, g1, bt1, nullptr, nullptr);
    aggstats_kernel<<<AGG_BLOCKS, 256>>>(hP, b2, aggP, 1);
    bnapply_kernel<<<(NN * 16 + 255) / 256, 256>>>(aggP, g2, bt2, out);
}

// round 14
// speedup vs baseline: 1.2082x; 1.0444x over previous
#include <cuda_runtime.h>
#include <cuda_bf16.h>
#include <cuda_fp16.h>
#include <math.h>
#include <stdint.h>

#define NN 100000
#define EE 1000000
#define INF 128
#define HH 64
#define BN_EPS 1e-5f
#define NB_BUILD 98

typedef unsigned long long ull;

// ---------------- scratch (device globals, no runtime alloc) ----------------
// Invariant: g_indeg is all-zero at every kernel_launch entry (zero-initialized at
// module load; build kernel re-zeros it after use on every execution).
// g_bar1 / g_ticket / g_flag are MONOTONIC (never reset; generation = value/NB_BUILD).
__device__ int   g_indeg[NN];
__device__ uint2 g_offcnt[NN];     // {csr offset, indegree}
__device__ int   g_rank[EE];
__device__ int   g_csr[EE];
__device__ float g_dinv[NN];
__device__ int   g_bsum[NB_BUILD];
__device__ int   g_boff[NB_BUILD];
__device__ int   g_bar1;
__device__ int   g_ticket;
__device__ int   g_flag;
__device__ float g_sum[2][HH];
__device__ float g_sq[2][HH];

__device__ __half2 g_h[(size_t)NN * 32];   // GEMM output (fp16 pairs), pre-scaled by dinv[row]
__device__ float   g_agg[(size_t)NN * HH]; // aggregation output (pre-BN, fp32)

// packed dual-fp32 add (Blackwell; ptxas never emits this from C++)
__device__ __forceinline__ ull add2(ull a, ull b) {
    ull d;
    asm("add.rn.f32x2 %0, %1, %2;" : "=l"(d) : "l"(a), "l"(b));
    return d;
}

// ---------------- fused graph build: hist + device barrier + scan ----------------
// 98 blocks x 1024 threads — single wave guaranteed, spins are safe.
__global__ __launch_bounds__(1024, 1)
void build_kernel(const int* __restrict__ dst) {
    __shared__ int sh[1024];
    __shared__ int sh_tgt;
    __shared__ int sh_gen;
    __shared__ int amLast;
    int t = threadIdx.x;
    int b = blockIdx.x;

    // per-call stats reset (consumed after GEMM1, safe here)
    if (b == 0 && t < 2 * HH) {
        ((float*)g_sum)[t] = 0.f;
        ((float*)g_sq)[t]  = 0.f;
    }

    // ---- phase 1: histogram + per-edge rank (grid-stride) ----
    for (int e = b * 1024 + t; e < EE; e += NB_BUILD * 1024)
        g_rank[e] = atomicAdd(&g_indeg[dst[e]], 1);

    // ---- device-wide barrier (monotonic generation counter) ----
    __syncthreads();
    if (t == 0) {
        __threadfence();
        int my = atomicAdd(&g_bar1, 1);
        sh_tgt = (my / NB_BUILD + 1) * NB_BUILD;
    }
    __syncthreads();
    if (t == 0) {
        while (atomicAdd(&g_bar1, 0) < sh_tgt) {}
    }
    __syncthreads();

    // ---- phase 2: block-local inclusive scan of indeg ----
    int idx = b * 1024 + t;
    int v = (idx < NN) ? g_indeg[idx] : 0;
    sh[t] = v;
    __syncthreads();
    for (int o = 1; o < 1024; o <<= 1) {
        int a = (t >= o) ? sh[t - o] : 0;
        __syncthreads();
        sh[t] += a;
        __syncthreads();
    }
    int incl = sh[t];
    if (t == 1023) {
        g_bsum[b] = incl;
        __threadfence();
        int my = atomicAdd(&g_ticket, 1);
        amLast = ((my % NB_BUILD) == NB_BUILD - 1);
        sh_gen = my / NB_BUILD;
    }
    __syncthreads();
    int gen = sh_gen;
    if (amLast) {
        int bv = (t < NB_BUILD) ? g_bsum[t] : 0;
        sh[t] = (t < 128) ? bv : 0;
        __syncthreads();
        for (int o = 1; o < 128; o <<= 1) {
            int a = (t >= o && t < 128) ? sh[t - o] : 0;
            __syncthreads();
            if (t < 128) sh[t] += a;
            __syncthreads();
        }
        if (t < NB_BUILD) g_boff[t] = sh[t] - bv;
        __threadfence();
        if (t == 0) atomicAdd(&g_flag, 1);
    }
    if (t == 0) {
        while (atomicAdd(&g_flag, 0) < gen + 1) {}
    }
    __syncthreads();
    if (idx < NN) {
        int off = g_boff[b] + incl - v;
        g_offcnt[idx] = make_uint2((unsigned)off, (unsigned)v);
        g_dinv[idx] = rsqrtf((float)(v + 1));   // deg = indeg + self-loop (GEMM epilogue)
        g_indeg[idx] = 0;                        // self-clean for next call
    }
}

// ---------------- HMMA GEMM (mma.sync m16n8k16, fp16 in / fp32 accum) ----------------

__device__ __forceinline__ uint32_t smem_u32(const void* p) {
    uint32_t a;
    asm("{ .reg .u64 t; cvta.to.shared.u64 t, %1; cvt.u32.u64 %0, t; }" : "=r"(a) : "l"(p));
    return a;
}

__device__ __forceinline__ void ldmat_x4(uint32_t& r0, uint32_t& r1, uint32_t& r2, uint32_t& r3,
                                         uint32_t addr) {
    asm volatile("ldmatrix.sync.aligned.m8n8.x4.shared.b16 {%0,%1,%2,%3}, [%4];"
                 : "=r"(r0), "=r"(r1), "=r"(r2), "=r"(r3) : "r"(addr));
}

__device__ __forceinline__ void mma_16816(float& c0, float& c1, float& c2, float& c3,
                                          uint32_t a0, uint32_t a1, uint32_t a2, uint32_t a3,
                                          uint32_t b0, uint32_t b1) {
    asm volatile("mma.sync.aligned.m16n8k16.row.col.f32.f16.f16.f32 "
                 "{%0,%1,%2,%3}, {%4,%5,%6,%7}, {%8,%9}, {%0,%1,%2,%3};"
                 : "+f"(c0), "+f"(c1), "+f"(c2), "+f"(c3)
                 : "r"(a0), "r"(a1), "r"(a2), "r"(a3), "r"(b0), "r"(b1));
}

template <int K, int DO_BN, int DO_FILL>
__global__ __launch_bounds__(256, 2)
void mma_gemm_kernel(const float* __restrict__ A, const float* __restrict__ W,
                     __half2* __restrict__ C,
                     const float* __restrict__ gamma, const float* __restrict__ beta,
                     const int* __restrict__ src, const int* __restrict__ dst) {
    extern __shared__ char smem[];
    const int KS = K + 8;
    const int A_OFF = 512;
    const int B_OFF = A_OFF + 128 * KS * 2;
    float* s_scale = (float*)(smem + 0);
    float* s_shift = (float*)(smem + 256);
    __half* As = (__half*)(smem + A_OFF);
    __half* Bs = (__half*)(smem + B_OFF);

    int t = threadIdx.x;
    int wid = t >> 5;
    int lane = t & 31;
    int m0 = blockIdx.x * 128;

    if (DO_BN) {
        if (t < 64) {
            float m   = g_sum[0][t] * (1.0f / NN);
            float var = g_sq[0][t] * (1.0f / NN) - m * m;
            float sc  = gamma[t] * rsqrtf(var + BN_EPS);
            s_scale[t] = sc;
            s_shift[t] = beta[t] - m * sc;
        }
        __syncthreads();
    }

    // ---- A tile: fp32 -> (BN+ReLU) -> fp16 ----
    const int QK = K / 4;
    for (int idx = t; idx < 128 * QK; idx += 256) {
        int r = idx / QK;
        int q = idx - r * QK;
        int k = q * 4;
        int row = m0 + r;
        float4 v = make_float4(0.f, 0.f, 0.f, 0.f);
        if (row < NN) v = *reinterpret_cast<const float4*>(A + (size_t)row * K + k);
        if (DO_BN) {
            v.x = fmaxf(fmaf(v.x, s_scale[k + 0], s_shift[k + 0]), 0.f);
            v.y = fmaxf(fmaf(v.y, s_scale[k + 1], s_shift[k + 1]), 0.f);
            v.z = fmaxf(fmaf(v.z, s_scale[k + 2], s_shift[k + 2]), 0.f);
            v.w = fmaxf(fmaf(v.w, s_scale[k + 3], s_shift[k + 3]), 0.f);
        }
        __half2 h01 = __floats2half2_rn(v.x, v.y);
        __half2 h23 = __floats2half2_rn(v.z, v.w);
        ull pk = (ull)(*reinterpret_cast<uint32_t*>(&h01)) |
                 ((ull)(*reinterpret_cast<uint32_t*>(&h23)) << 32);
        *reinterpret_cast<ull*>(&As[r * KS + k]) = pk;
    }

    // ---- B tile = W^T: Bs[n][k] = W[k][n] ----
    for (int idx = t; idx < K * 64; idx += 256) {
        int k = idx >> 6;
        int n = idx & 63;
        Bs[n * KS + k] = __float2half_rn(W[idx]);
    }
    __syncthreads();

    float acc[8][4];
#pragma unroll
    for (int nb = 0; nb < 8; nb++)
#pragma unroll
        for (int j = 0; j < 4; j++) acc[nb][j] = 0.f;

    uint32_t as_base = smem_u32(As);
    uint32_t bs_base = smem_u32(Bs);

    uint32_t a_row = wid * 16 + (lane & 15);
    uint32_t a_addr0 = as_base + (a_row * KS + (lane >> 4) * 8) * 2;
    uint32_t b_n = (lane & 7) + ((lane >> 4) & 1) * 8;
    uint32_t b_k = ((lane >> 3) & 1) * 8;
    uint32_t b_addr0 = bs_base + (b_n * KS + b_k) * 2;

#pragma unroll
    for (int ks = 0; ks < K / 16; ks++) {
        uint32_t a0, a1, a2, a3;
        ldmat_x4(a0, a1, a2, a3, a_addr0 + ks * 32);
#pragma unroll
        for (int nb2 = 0; nb2 < 4; nb2++) {
            uint32_t b0, b1, b2, b3;
            ldmat_x4(b0, b1, b2, b3, b_addr0 + (nb2 * 16 * KS + ks * 16) * 2);
            mma_16816(acc[nb2 * 2 + 0][0], acc[nb2 * 2 + 0][1], acc[nb2 * 2 + 0][2], acc[nb2 * 2 + 0][3],
                      a0, a1, a2, a3, b0, b1);
            mma_16816(acc[nb2 * 2 + 1][0], acc[nb2 * 2 + 1][1], acc[nb2 * 2 + 1][2], acc[nb2 * 2 + 1][3],
                      a0, a1, a2, a3, b2, b3);
        }
    }

    int g = lane >> 2;
    int tq = lane & 3;
    int row0 = m0 + wid * 16 + g;
    int row1 = row0 + 8;
    if (row0 < NN) {
        float di = g_dinv[row0];
#pragma unroll
        for (int nb = 0; nb < 8; nb++)
            C[(size_t)row0 * 32 + nb * 4 + tq] = __floats2half2_rn(acc[nb][0] * di, acc[nb][1] * di);
    }
    if (row1 < NN) {
        float di = g_dinv[row1];
#pragma unroll
        for (int nb = 0; nb < 8; nb++)
            C[(size_t)row1 * 32 + nb * 4 + tq] = __floats2half2_rn(acc[nb][2] * di, acc[nb][3] * di);
    }

    // ---- fused CSR fill (independent; overlaps other blocks' MMA) ----
    if (DO_FILL) {
        int stride = gridDim.x * 256;
        for (int e = blockIdx.x * 256 + t; e < EE; e += stride)
            g_csr[g_offcnt[dst[e]].x + g_rank[e]] = src[e];
    }
}

// ---------------- aggregation: half-warp per node, fp16 gather, f32x2 accum + BN stats ----------------
// Each half-warp owns an independent node stream; 16 lanes x uint2(8B) cover a 128B fp16 row
// (2 L1 wavefronts per warp-gather vs 4 for fp32). Accumulation in packed fp32.
__global__ __launch_bounds__(256, 6)
void aggstats_kernel(const __half2* __restrict__ h, const float* __restrict__ bias,
                     float* __restrict__ out, int layer) {
    __shared__ float s_sum[64], s_sq[64];
    int t = threadIdx.x;
    if (t < 64) { s_sum[t] = 0.f; s_sq[t] = 0.f; }
    __syncthreads();
    int c4 = t & 15;             // uint2 slot: channels 4*c4 .. 4*c4+3
    int hwId = (blockIdx.x * blockDim.x + t) >> 4;
    int totalHW = (gridDim.x * blockDim.x) >> 4;
    const uint2* h4 = reinterpret_cast<const uint2*>(h);  // 16 uint2 per row
    float4 b4 = reinterpret_cast<const float4*>(bias)[c4];
    float sm0 = 0.f, sm1 = 0.f, sm2 = 0.f, sm3 = 0.f;
    float sq0 = 0.f, sq1 = 0.f, sq2 = 0.f, sq3 = 0.f;

    for (int i = hwId; i < NN; i += totalHW) {
        uint2 oc = g_offcnt[i];
        int e0 = (int)oc.x;
        int e1 = e0 + (int)oc.y;
        float di = rsqrtf((float)(oc.y + 1u));
        uint2 sv = h4[(unsigned)i * 16u + c4];       // self-loop (pre-scaled)
        float2 f0 = __half22float2(*reinterpret_cast<__half2*>(&sv.x));
        float2 f1 = __half22float2(*reinterpret_cast<__half2*>(&sv.y));
        ulonglong2 a2;
        a2.x = *reinterpret_cast<ull*>(&f0);
        a2.y = *reinterpret_cast<ull*>(&f1);
        int j = e0;
        for (; j + 3 < e1; j += 4) {
            int s0 = g_csr[j], s1 = g_csr[j + 1], s2 = g_csr[j + 2], s3 = g_csr[j + 3];
            uint2 v0 = h4[(unsigned)s0 * 16u + c4];
            uint2 v1 = h4[(unsigned)s1 * 16u + c4];
            uint2 v2 = h4[(unsigned)s2 * 16u + c4];
            uint2 v3 = h4[(unsigned)s3 * 16u + c4];
            float2 p0 = __half22float2(*reinterpret_cast<__half2*>(&v0.x));
            float2 p1 = __half22float2(*reinterpret_cast<__half2*>(&v0.y));
            float2 q0 = __half22float2(*reinterpret_cast<__half2*>(&v1.x));
            float2 q1 = __half22float2(*reinterpret_cast<__half2*>(&v1.y));
            float2 r0 = __half22float2(*reinterpret_cast<__half2*>(&v2.x));
            float2 r1 = __half22float2(*reinterpret_cast<__half2*>(&v2.y));
            float2 w0 = __half22float2(*reinterpret_cast<__half2*>(&v3.x));
            float2 w1 = __half22float2(*reinterpret_cast<__half2*>(&v3.y));
            ull u0x = add2(*reinterpret_cast<ull*>(&p0), *reinterpret_cast<ull*>(&q0));
            ull u0y = add2(*reinterpret_cast<ull*>(&p1), *reinterpret_cast<ull*>(&q1));
            ull u2x = add2(*reinterpret_cast<ull*>(&r0), *reinterpret_cast<ull*>(&w0));
            ull u2y = add2(*reinterpret_cast<ull*>(&r1), *reinterpret_cast<ull*>(&w1));
            a2.x = add2(a2.x, add2(u0x, u2x));
            a2.y = add2(a2.y, add2(u0y, u2y));
        }
        for (; j < e1; j++) {
            uint2 v = h4[(unsigned)g_csr[j] * 16u + c4];
            float2 p0 = __half22float2(*reinterpret_cast<__half2*>(&v.x));
            float2 p1 = __half22float2(*reinterpret_cast<__half2*>(&v.y));
            a2.x = add2(a2.x, *reinterpret_cast<ull*>(&p0));
            a2.y = add2(a2.y, *reinterpret_cast<ull*>(&p1));
        }
        float2 acc0 = *reinterpret_cast<float2*>(&a2.x);
        float2 acc1 = *reinterpret_cast<float2*>(&a2.y);
        float4 o;
        o.x = fmaf(acc0.x, di, b4.x);
        o.y = fmaf(acc0.y, di, b4.y);
        o.z = fmaf(acc1.x, di, b4.z);
        o.w = fmaf(acc1.y, di, b4.w);
        reinterpret_cast<float4*>(out)[(unsigned)i * 16u + c4] = o;
        sm0 += o.x; sq0 += o.x * o.x;
        sm1 += o.y; sq1 += o.y * o.y;
        sm2 += o.z; sq2 += o.z * o.z;
        sm3 += o.w; sq3 += o.w * o.w;
    }
    atomicAdd(&s_sum[c4 * 4 + 0], sm0);
    atomicAdd(&s_sum[c4 * 4 + 1], sm1);
    atomicAdd(&s_sum[c4 * 4 + 2], sm2);
    atomicAdd(&s_sum[c4 * 4 + 3], sm3);
    atomicAdd(&s_sq [c4 * 4 + 0], sq0);
    atomicAdd(&s_sq [c4 * 4 + 1], sq1);
    atomicAdd(&s_sq [c4 * 4 + 2], sq2);
    atomicAdd(&s_sq [c4 * 4 + 3], sq3);
    __syncthreads();
    if (t < 64) {
        atomicAdd(&g_sum[layer][t], s_sum[t]);
        atomicAdd(&g_sq[layer][t], s_sq[t]);
    }
}

// BN apply with in-block prep: scale/shift from g_sum[1]/g_sq[1]
__global__ void bnapply_kernel(const float* __restrict__ v,
                               const float* __restrict__ gamma, const float* __restrict__ beta,
                               float* __restrict__ out) {
    __shared__ float sc[64], sf[64];
    int t = threadIdx.x;
    if (t < 64) {
        float m   = g_sum[1][t] * (1.0f / NN);
        float var = g_sq[1][t] * (1.0f / NN) - m * m;
        float s   = gamma[t] * rsqrtf(var + BN_EPS);
        sc[t] = s;
        sf[t] = beta[t] - m * s;
    }
    __syncthreads();
    int idx = blockIdx.x * blockDim.x + t;
    if (idx >= NN * 16) return;
    float4 x = reinterpret_cast<const float4*>(v)[idx];
    int c = (idx & 15) * 4;
    x.x = fmaxf(fmaf(x.x, sc[c + 0], sf[c + 0]), 0.f);
    x.y = fmaxf(fmaf(x.y, sc[c + 1], sf[c + 1]), 0.f);
    x.z = fmaxf(fmaf(x.z, sc[c + 2], sf[c + 2]), 0.f);
    x.w = fmaxf(fmaf(x.w, sc[c + 3], sf[c + 3]), 0.f);
    reinterpret_cast<float4*>(out)[idx] = x;
}

// ---------------- launch ----------------
extern "C" void kernel_launch(void* const* d_in, const int* in_sizes, int n_in,
                              void* d_out, int out_size) {
    const float* x   = (const float*)d_in[0];
    const int*   ei  = (const int*)d_in[1];
    const float* W1  = (const float*)d_in[2];
    const float* b1  = (const float*)d_in[3];
    const float* g1  = (const float*)d_in[4];
    const float* bt1 = (const float*)d_in[5];
    const float* W2  = (const float*)d_in[6];
    const float* b2  = (const float*)d_in[7];
    const float* g2  = (const float*)d_in[8];
    const float* bt2 = (const float*)d_in[9];
    float* out = (float*)d_out;

    const int* src = ei;
    const int* dst = ei + EE;

    __half2* hP = nullptr;
    float* aggP = nullptr;
    cudaGetSymbolAddress((void**)&hP, g_h);
    cudaGetSymbolAddress((void**)&aggP, g_agg);

    const int AGG_BLOCKS = 888;
    const int SMEM1 = 512 + 128 * (INF + 8) * 2 + 64 * (INF + 8) * 2;  // 52736
    const int SMEM2 = 512 + 128 * (HH + 8) * 2 + 64 * (HH + 8) * 2;    // 28160

    cudaFuncSetAttribute(mma_gemm_kernel<INF, 0, 1>,
                         cudaFuncAttributeMaxDynamicSharedMemorySize, SMEM1);
    cudaFuncSetAttribute(mma_gemm_kernel<HH, 1, 0>,
                         cudaFuncAttributeMaxDynamicSharedMemorySize, SMEM2);

    // fused hist + scan (device-wide barrier inside; 98 blocks = single wave)
    build_kernel<<<NB_BUILD, 1024>>>(dst);

    // ---- layer 1 (CSR fill fused into GEMM1) ----
    mma_gemm_kernel<INF, 0, 1><<<(NN + 127) / 128, 256, SMEM1>>>(x, W1, hP, nullptr, nullptr, src, dst);
    aggstats_kernel<<<AGG_BLOCKS, 256>>>(hP, b1, aggP, 0);

    // ---- layer 2: BN(layer1)+ReLU fused into A-tile load ----
    mma_gemm_kernel<HH, 1, 0><<<(NN + 127) / 128, 256, SMEM2>>>(aggP, W2, hP, g1, bt1, nullptr, nullptr);
    aggstats_kernel<<<AGG_BLOCKS, 256>>>(hP, b2, aggP, 1);
    bnapply_kernel<<<(NN * 16 + 255) / 256, 256>>>(aggP, g2, bt2, out);
}